// round 10
// baseline (speedup 1.0000x reference)
#include <cuda_runtime.h>
#include <cuda_bf16.h>
#include <math.h>
#include <cstdint>

#define NPTS 4096
#define LCH  512
#define ICH  1024
#define HWD  256
#define HEADS 4

// ========================= helpers =========================================
__device__ __forceinline__ uint32_t smem_to_u32(const void* smem_ptr) {
    uint32_t addr;
    asm("{ .reg .u64 tmp; cvta.to.shared.u64 tmp, %1; cvt.u32.u64 %0, tmp; }"
        : "=r"(addr) : "l"(smem_ptr));
    return addr;
}
__device__ __forceinline__ void cp_async16(uint32_t dst_smem, const void* src) {
    asm volatile("cp.async.cg.shared.global [%0], [%1], 16;"
        :: "r"(dst_smem), "l"((unsigned long long)__cvta_generic_to_global(src)) : "memory");
}
#define CP_ASYNC_COMMIT() asm volatile("cp.async.commit_group;" ::: "memory")
#define CP_ASYNC_WAIT(n)  asm volatile("cp.async.wait_group %0;" :: "n"(n) : "memory")

__device__ __forceinline__ void ldsm_x4(uint32_t (&r)[4], uint32_t addr) {
    asm volatile("ldmatrix.sync.aligned.m8n8.x4.shared.b16 {%0,%1,%2,%3}, [%4];"
        : "=r"(r[0]), "=r"(r[1]), "=r"(r[2]), "=r"(r[3]) : "r"(addr));
}
__device__ __forceinline__ void ldsm_x2(uint32_t (&r)[2], uint32_t addr) {
    asm volatile("ldmatrix.sync.aligned.m8n8.x2.shared.b16 {%0,%1}, [%2];"
        : "=r"(r[0]), "=r"(r[1]) : "r"(addr));
}
__device__ __forceinline__ void mma_bf16(float (&d)[4], const uint32_t (&a)[4],
                                         const uint32_t (&b)[2]) {
    asm volatile(
        "mma.sync.aligned.m16n8k16.row.col.f32.bf16.bf16.f32 "
        "{%0,%1,%2,%3}, {%4,%5,%6,%7}, {%8,%9}, {%0,%1,%2,%3};"
        : "+f"(d[0]), "+f"(d[1]), "+f"(d[2]), "+f"(d[3])
        : "r"(a[0]), "r"(a[1]), "r"(a[2]), "r"(a[3]), "r"(b[0]), "r"(b[1]));
}

// ========================= scratch globals =================================
__device__ float g_img [ICH * NPTS];
__device__ float g_Lq  [LCH * NPTS];
__device__ float g_keys[HEADS * LCH * NPTS];
__device__ float g_t   [LCH * NPTS];
__device__ float g_wmap[HEADS * NPTS];
__device__ float g_spart[8][HEADS][NPTS];    // partial scores

__device__ __nv_bfloat16 g_wK_hi[HEADS * LCH * ICH], g_wK_lo[HEADS * LCH * ICH];
__device__ __nv_bfloat16 g_wL_hi[LCH * LCH],         g_wL_lo[LCH * LCH];
__device__ __nv_bfloat16 g_wF_hi[LCH * LCH],         g_wF_lo[LCH * LCH];
__device__ __nv_bfloat16 g_imgT_hi[NPTS * ICH],      g_imgT_lo[NPTS * ICH];
__device__ __nv_bfloat16 g_pfT_hi [NPTS * LCH],      g_pfT_lo [NPTS * LCH];
__device__ __nv_bfloat16 g_tT_hi  [NPTS * LCH],      g_tT_lo  [NPTS * LCH];

// ========================= gather (prep inlined) ===========================
__global__ void gather_bev(const float* __restrict__ bev, const float* __restrict__ kp) {
    int n = blockIdx.x * blockDim.x + threadIdx.x;   // 0..4095
    int c = blockIdx.y;                               // 0..1023
    float x = kp[n * 4 + 1] * 256.0f;
    float y = kp[n * 4 + 2] * 256.0f;
    int fx = (int)floorf(x);
    int fy = (int)floorf(y);
    int x0 = min(max(fx,     0), HWD - 1);
    int x1 = min(max(fx + 1, 0), HWD - 1);
    int y0 = min(max(fy,     0), HWD - 1);
    int y1 = min(max(fy + 1, 0), HWD - 1);
    float x0f = (float)x0, x1f = (float)x1, y0f = (float)y0, y1f = (float)y1;
    float wa = (x1f - x) * (y1f - y);
    float wb = (x1f - x) * (y - y0f);
    float wc = (x - x0f) * (y1f - y);
    float wd = (x - x0f) * (y - y0f);
    const float* pl = bev + (size_t)c * (HWD * HWD);
    float v = wa * pl[y0 * HWD + x0]
            + wb * pl[y1 * HWD + x0]
            + wc * pl[y0 * HWD + x1]
            + wd * pl[y1 * HWD + x1];
    g_img[(size_t)c * NPTS + n] = v;
}

// ========================= converts ========================================
__global__ void cvt_weights(const float* __restrict__ wK, const float* __restrict__ wL,
                            const float* __restrict__ wF) {
    int i = blockIdx.x * blockDim.x + threadIdx.x;
    const int CK = HEADS * LCH * ICH;
    const int CL = LCH * LCH;
    const float* src; __nv_bfloat16 *hi, *lo; int j;
    if (i < CK)            { src = wK; hi = g_wK_hi; lo = g_wK_lo; j = i; }
    else if (i < CK + CL)  { src = wL; hi = g_wL_hi; lo = g_wL_lo; j = i - CK; }
    else if (i < CK + 2*CL){ src = wF; hi = g_wF_hi; lo = g_wF_lo; j = i - CK - CL; }
    else return;
    float v = src[j];
    __nv_bfloat16 h = __float2bfloat16(v);
    hi[j] = h;
    lo[j] = __float2bfloat16(v - __bfloat162float(h));
}

// fused transpose+split of pf (K=512) and img (K=1024)
__global__ __launch_bounds__(256)
void cvt_acts(const float* __restrict__ pf) {
    __shared__ float tile[32][33];
    const float* src; __nv_bfloat16 *hiT, *loT; int K, k0;
    if (blockIdx.y < 16) { src = pf;    hiT = g_pfT_hi;  loT = g_pfT_lo;  K = LCH; k0 = blockIdx.y * 32; }
    else                 { src = g_img; hiT = g_imgT_hi; loT = g_imgT_lo; K = ICH; k0 = (blockIdx.y - 16) * 32; }
    int n0 = blockIdx.x * 32;
    int tx = threadIdx.x & 31;
    int ty = threadIdx.x >> 5;
    #pragma unroll
    for (int j = 0; j < 4; j++) {
        int k = k0 + ty + j * 8;
        tile[ty + j * 8][tx] = src[(size_t)k * NPTS + n0 + tx];
    }
    __syncthreads();
    #pragma unroll
    for (int j = 0; j < 4; j++) {
        int n = n0 + ty + j * 8;
        float v = tile[tx][ty + j * 8];
        __nv_bfloat16 h = __float2bfloat16(v);
        hiT[(size_t)n * K + k0 + tx] = h;
        loT[(size_t)n * K + k0 + tx] = __float2bfloat16(v - __bfloat162float(h));
    }
}

__global__ __launch_bounds__(256)
void cvt_split_T(const float* __restrict__ src,
                 __nv_bfloat16* __restrict__ hiT,
                 __nv_bfloat16* __restrict__ loT, int K, int N) {
    __shared__ float tile[32][33];
    int n0 = blockIdx.x * 32;
    int k0 = blockIdx.y * 32;
    int tx = threadIdx.x & 31;
    int ty = threadIdx.x >> 5;
    #pragma unroll
    for (int j = 0; j < 4; j++) {
        int k = k0 + ty + j * 8;
        tile[ty + j * 8][tx] = src[(size_t)k * N + n0 + tx];
    }
    __syncthreads();
    #pragma unroll
    for (int j = 0; j < 4; j++) {
        int n = n0 + ty + j * 8;
        float v = tile[tx][ty + j * 8];
        __nv_bfloat16 h = __float2bfloat16(v);
        hiT[(size_t)n * K + k0 + tx] = h;
        loT[(size_t)n * K + k0 + tx] = __float2bfloat16(v - __bfloat162float(h));
    }
}

// ========================= mma.sync split-bf16 GEMM ========================
// 4-stage cp.async pipeline, K-chunk 16 (48B padded rows, conflict-free ldsm)
#define RSB    48                     // 32B data + 16B pad
#define TILEB  (128 * RSB)            // 6144 B per operand tile
#define STAGEB (4 * TILEB)            // 24576: Ahi Alo Bhi Blo
#define NSTAGE 4
#define GEMM_SMEM (NSTAGE * STAGEB)   // 98304

__device__ __forceinline__
void gemm_body(const __nv_bfloat16* __restrict__ Ahi,
               const __nv_bfloat16* __restrict__ Alo,
               const __nv_bfloat16* __restrict__ Bhi,
               const __nv_bfloat16* __restrict__ Blo,
               const float* __restrict__ bias,
               float* __restrict__ C, int bm, int bn, int N, int K) {
    extern __shared__ char smem[];
    uint32_t sb = smem_to_u32(smem);

    int tid = threadIdx.x;
    int lane = tid & 31, wid = tid >> 5;
    int warp_m = wid & 1;           // 64-row slab
    int warp_n = wid >> 1;          // 32-col slab

    uint32_t aOff[4], bOff[4];
    #pragma unroll
    for (int mi = 0; mi < 4; mi++) {
        int row = warp_m * 64 + mi * 16 + (lane & 15);
        aOff[mi] = (uint32_t)(row * RSB + (lane >> 4) * 16);
    }
    #pragma unroll
    for (int ni = 0; ni < 4; ni++) {
        int row = warp_n * 32 + ni * 8 + (lane & 7);
        bOff[ni] = (uint32_t)(row * RSB + ((lane >> 3) & 1) * 16);
    }

    float acc[4][4][4];
    #pragma unroll
    for (int mi = 0; mi < 4; mi++)
        #pragma unroll
        for (int ni = 0; ni < 4; ni++)
            #pragma unroll
            for (int j = 0; j < 4; j++) acc[mi][ni][j] = 0.0f;

    // loader: per tile 128 rows x 2 segs of 16B; 256 threads -> 1 xfer/tile
    int ldRow = tid >> 1;
    int ldSeg = tid & 1;
    uint32_t ldSo = (uint32_t)(ldRow * RSB + ldSeg * 16);
    int nchunks = K >> 4;

    auto load_stage = [&](int stage, int k0) {
        uint32_t s = sb + stage * STAGEB;
        size_t goA = (size_t)(bm + ldRow) * K + k0 + ldSeg * 8;
        size_t goB = (size_t)(bn + ldRow) * K + k0 + ldSeg * 8;
        cp_async16(s + 0 * TILEB + ldSo, Ahi + goA);
        cp_async16(s + 1 * TILEB + ldSo, Alo + goA);
        cp_async16(s + 2 * TILEB + ldSo, Bhi + goB);
        cp_async16(s + 3 * TILEB + ldSo, Blo + goB);
    };

    #pragma unroll
    for (int p = 0; p < 3; p++) {
        load_stage(p, p << 4);
        CP_ASYNC_COMMIT();
    }

    for (int c = 0; c < nchunks; c++) {
        int rem = nchunks - 1 - c;
        if (rem >= 2)      { CP_ASYNC_WAIT(2); }
        else if (rem == 1) { CP_ASYNC_WAIT(1); }
        else               { CP_ASYNC_WAIT(0); }
        __syncthreads();

        if (c + 3 < nchunks) {
            load_stage((c + 3) & (NSTAGE - 1), (c + 3) << 4);
            CP_ASYNC_COMMIT();
        }

        uint32_t s = sb + (c & (NSTAGE - 1)) * STAGEB;
        uint32_t sAh = s, sAl = s + TILEB, sBh = s + 2 * TILEB, sBl = s + 3 * TILEB;

        uint32_t a[4][4], bh[4][2], bl[4][2];
        #pragma unroll
        for (int mi = 0; mi < 4; mi++) ldsm_x4(a[mi], sAh + aOff[mi]);
        #pragma unroll
        for (int ni = 0; ni < 4; ni++) ldsm_x2(bh[ni], sBh + bOff[ni]);
        #pragma unroll
        for (int ni = 0; ni < 4; ni++) ldsm_x2(bl[ni], sBl + bOff[ni]);
        #pragma unroll
        for (int mi = 0; mi < 4; mi++)
            #pragma unroll
            for (int ni = 0; ni < 4; ni++) mma_bf16(acc[mi][ni], a[mi], bh[ni]);
        #pragma unroll
        for (int mi = 0; mi < 4; mi++)
            #pragma unroll
            for (int ni = 0; ni < 4; ni++) mma_bf16(acc[mi][ni], a[mi], bl[ni]);
        #pragma unroll
        for (int mi = 0; mi < 4; mi++) ldsm_x4(a[mi], sAl + aOff[mi]);
        #pragma unroll
        for (int mi = 0; mi < 4; mi++)
            #pragma unroll
            for (int ni = 0; ni < 4; ni++) mma_bf16(acc[mi][ni], a[mi], bh[ni]);
    }

    int lr = lane >> 2, lc = (lane & 3) * 2;
    int r0 = bm + warp_m * 64;
    int c0 = bn + warp_n * 32;
    #pragma unroll
    for (int mi = 0; mi < 4; mi++) {
        int m1 = r0 + mi * 16 + lr;
        int m2 = m1 + 8;
        float bv1 = bias[m1];
        float bv2 = bias[m2];
        #pragma unroll
        for (int ni = 0; ni < 4; ni++) {
            int n = c0 + ni * 8 + lc;
            float2 v1 = make_float2(acc[mi][ni][0] + bv1, acc[mi][ni][1] + bv1);
            float2 v2 = make_float2(acc[mi][ni][2] + bv2, acc[mi][ni][3] + bv2);
            *(float2*)(C + (size_t)m1 * N + n) = v1;
            *(float2*)(C + (size_t)m2 * N + n) = v2;
        }
    }
}

// combined launch: blocks [0,512) -> keys GEMM; [512,640) -> L_query GEMM.
// Pointer-select branch, then ONE gemm_body call (no code duplication).
__global__ __launch_bounds__(256, 2)
void gemm_dual(const float* __restrict__ convLb, const float* __restrict__ imgHb) {
    const __nv_bfloat16 *Ahi, *Alo, *Bhi, *Blo;
    const float* bias;
    float* C;
    int bm, bn, K;
    int b = blockIdx.x;
    if (b < 512) {
        Ahi = g_wK_hi; Alo = g_wK_lo; Bhi = g_imgT_hi; Blo = g_imgT_lo;
        bias = imgHb; C = g_keys; K = ICH;
        bm = (b >> 5) * 128; bn = (b & 31) * 128;
    } else {
        int j = b - 512;
        Ahi = g_wL_hi; Alo = g_wL_lo; Bhi = g_pfT_hi; Blo = g_pfT_lo;
        bias = convLb; C = g_Lq; K = LCH;
        bm = (j >> 5) * 128; bn = (j & 31) * 128;
    }
    gemm_body(Ahi, Alo, Bhi, Blo, bias, C, bm, bn, NPTS, K);
}

__global__ __launch_bounds__(256, 2)
void gemm_single(const __nv_bfloat16* __restrict__ Ahi, const __nv_bfloat16* __restrict__ Alo,
                 const __nv_bfloat16* __restrict__ Bhi, const __nv_bfloat16* __restrict__ Blo,
                 const float* __restrict__ bias, float* __restrict__ C, int N, int K) {
    gemm_body(Ahi, Alo, Bhi, Blo, bias, C, blockIdx.y * 128, blockIdx.x * 128, N, K);
}

// ========================= attention tail ==================================
__global__ void score_part() {
    int n = blockIdx.x * blockDim.x + threadIdx.x;
    int l0 = blockIdx.y * 64;
    float a0 = 0.f, a1 = 0.f, a2 = 0.f, a3 = 0.f;
    for (int l = l0; l < l0 + 64; l++) {
        float lq = g_Lq[l * NPTS + n];
        a0 += g_keys[(0 * LCH + l) * NPTS + n] * lq;
        a1 += g_keys[(1 * LCH + l) * NPTS + n] * lq;
        a2 += g_keys[(2 * LCH + l) * NPTS + n] * lq;
        a3 += g_keys[(3 * LCH + l) * NPTS + n] * lq;
    }
    g_spart[blockIdx.y][0][n] = a0;
    g_spart[blockIdx.y][1][n] = a1;
    g_spart[blockIdx.y][2][n] = a2;
    g_spart[blockIdx.y][3][n] = a3;
}

__global__ void softmax_k() {
    int n = blockIdx.x * blockDim.x + threadIdx.x;
    float a0 = 0.f, a1 = 0.f, a2 = 0.f, a3 = 0.f;
    #pragma unroll
    for (int p = 0; p < 8; p++) {
        a0 += g_spart[p][0][n];
        a1 += g_spart[p][1][n];
        a2 += g_spart[p][2][n];
        a3 += g_spart[p][3][n];
    }
    const float inv = 0.04419417382415922f;  // 1/sqrt(512)
    a0 *= inv; a1 *= inv; a2 *= inv; a3 *= inv;
    float m = fmaxf(fmaxf(a0, a1), fmaxf(a2, a3));
    float e0 = expf(a0 - m), e1 = expf(a1 - m), e2 = expf(a2 - m), e3 = expf(a3 - m);
    float s = e0 + e1 + e2 + e3;
    g_wmap[0 * NPTS + n] = e0 / s;
    g_wmap[1 * NPTS + n] = e1 / s;
    g_wmap[2 * NPTS + n] = e2 / s;
    g_wmap[3 * NPTS + n] = e3 / s;
}

__global__ void compute_t() {
    size_t i = (size_t)blockIdx.x * blockDim.x + threadIdx.x;
    int n = (int)(i & (NPTS - 1));
    float w0 = g_wmap[0 * NPTS + n];
    float w1 = g_wmap[1 * NPTS + n];
    float w2 = g_wmap[2 * NPTS + n];
    float w3 = g_wmap[3 * NPTS + n];
    const size_t HS = (size_t)LCH * NPTS;
    float z = w0 * g_keys[i] + w1 * g_keys[HS + i]
            + w2 * g_keys[2 * HS + i] + w3 * g_keys[3 * HS + i];
    g_t[i] = z + g_Lq[i];
}

__global__ __launch_bounds__(256)
void layernorm(const float* __restrict__ lnw, const float* __restrict__ lnb) {
    int l = blockIdx.x;
    float* row = g_t + (size_t)l * NPTS;
    float s = 0.f, ss = 0.f;
    for (int n = threadIdx.x; n < NPTS; n += 256) {
        float v = row[n];
        s += v; ss += v * v;
    }
    __shared__ float rs[8], rss[8];
    for (int o = 16; o > 0; o >>= 1) {
        s  += __shfl_down_sync(0xffffffffu, s,  o);
        ss += __shfl_down_sync(0xffffffffu, ss, o);
    }
    int wid = threadIdx.x >> 5, lid = threadIdx.x & 31;
    if (lid == 0) { rs[wid] = s; rss[wid] = ss; }
    __syncthreads();
    if (wid == 0) {
        s  = (lid < 8) ? rs[lid]  : 0.f;
        ss = (lid < 8) ? rss[lid] : 0.f;
        for (int o = 4; o > 0; o >>= 1) {
            s  += __shfl_down_sync(0xffffffffu, s,  o);
            ss += __shfl_down_sync(0xffffffffu, ss, o);
        }
        if (lid == 0) { rs[0] = s; rss[0] = ss; }
    }
    __syncthreads();
    float mu = rs[0] * (1.0f / NPTS);
    float var = rss[0] * (1.0f / NPTS) - mu * mu;
    float rstd = rsqrtf(var + 1e-5f);
    for (int n = threadIdx.x; n < NPTS; n += 256)
        row[n] = (row[n] - mu) * rstd * lnw[n] + lnb[n];
}

__global__ void copy_wmap(float* __restrict__ out) {
    int i = blockIdx.x * blockDim.x + threadIdx.x;
    if (i < HEADS * NPTS) out[i] = g_wmap[i];
}

// ========================= launch ==========================================
extern "C" void kernel_launch(void* const* d_in, const int* in_sizes, int n_in,
                              void* d_out, int out_size) {
    const float* point_features = (const float*)d_in[0];
    const float* keypoints      = (const float*)d_in[1];
    const float* bev_features   = (const float*)d_in[2];
    const float* conv_L_w       = (const float*)d_in[3];
    const float* conv_L_b       = (const float*)d_in[4];
    const float* img_head_w     = (const float*)d_in[5];
    const float* img_head_b     = (const float*)d_in[6];
    const float* ln_w           = (const float*)d_in[7];
    const float* ln_b           = (const float*)d_in[8];
    const float* conv_fusion_w  = (const float*)d_in[9];
    const float* conv_fusion_b  = (const float*)d_in[10];
    float* out = (float*)d_out;

    cudaFuncSetAttribute(gemm_dual,   cudaFuncAttributeMaxDynamicSharedMemorySize, GEMM_SMEM);
    cudaFuncSetAttribute(gemm_single, cudaFuncAttributeMaxDynamicSharedMemorySize, GEMM_SMEM);

    float *p_t;
    cudaGetSymbolAddress((void**)&p_t, g_t);
    __nv_bfloat16 *wFh, *wFl, *tTh, *tTl;
    cudaGetSymbolAddress((void**)&wFh, g_wF_hi);  cudaGetSymbolAddress((void**)&wFl, g_wF_lo);
    cudaGetSymbolAddress((void**)&tTh, g_tT_hi);  cudaGetSymbolAddress((void**)&tTl, g_tT_lo);

    // 1) BEV gather (bilinear params inlined)
    gather_bev<<<dim3(NPTS / 256, ICH), 256>>>(bev_features, keypoints);
    // 2) weight splits
    {
        int count = HEADS * LCH * ICH + 2 * LCH * LCH;
        cvt_weights<<<(count + 255) / 256, 256>>>(img_head_w, conv_L_w, conv_fusion_w);
    }
    // 3) pf + img transpose/split
    cvt_acts<<<dim3(NPTS / 32, 48), 256>>>(point_features);
    // 4) keys + L_query GEMMs in one launch  (profiled slot #4)
    gemm_dual<<<640, 256, GEMM_SMEM>>>(conv_L_b, img_head_b);
    // 5) partial scores (128 CTAs)
    score_part<<<dim3(NPTS / 256, 8), 256>>>();
    // 6) softmax over heads
    softmax_k<<<NPTS / 256, 256>>>();
    // 7) t = z + L_query (parallel)
    compute_t<<<(LCH * NPTS) / 256, 256>>>();
    // 8) LayerNorm over point axis
    layernorm<<<LCH, 256>>>(ln_w, ln_b);
    // 9) t transpose/split
    cvt_split_T<<<dim3(NPTS / 32, LCH / 32), 256>>>(p_t, tTh, tTl, LCH, NPTS);
    // 10) fusion GEMM -> out
    gemm_single<<<dim3(NPTS / 128, LCH / 128), 256, GEMM_SMEM>>>(
        wFh, wFl, tTh, tTl, conv_fusion_b, out, NPTS, LCH);
    // 11) weightmap tail
    if (out_size >= LCH * NPTS + HEADS * NPTS) {
        copy_wmap<<<(HEADS * NPTS + 255) / 256, 256>>>(out + (size_t)LCH * NPTS);
    }
}

// round 11
// speedup vs baseline: 1.5693x; 1.5693x over previous
#include <cuda_runtime.h>
#include <cuda_bf16.h>
#include <cuda_fp16.h>
#include <math.h>
#include <cstdint>

#define NPTS 4096
#define LCH  512
#define ICH  1024
#define HWD  256
#define HEADS 4

// ========================= helpers =========================================
__device__ __forceinline__ uint32_t smem_to_u32(const void* smem_ptr) {
    uint32_t addr;
    asm("{ .reg .u64 tmp; cvta.to.shared.u64 tmp, %1; cvt.u32.u64 %0, tmp; }"
        : "=r"(addr) : "l"(smem_ptr));
    return addr;
}
__device__ __forceinline__ void cp_async16(uint32_t dst_smem, const void* src) {
    asm volatile("cp.async.cg.shared.global [%0], [%1], 16;"
        :: "r"(dst_smem), "l"((unsigned long long)__cvta_generic_to_global(src)) : "memory");
}
#define CP_ASYNC_COMMIT() asm volatile("cp.async.commit_group;" ::: "memory")
#define CP_ASYNC_WAIT(n)  asm volatile("cp.async.wait_group %0;" :: "n"(n) : "memory")

__device__ __forceinline__ void ldsm_x4(uint32_t (&r)[4], uint32_t addr) {
    asm volatile("ldmatrix.sync.aligned.m8n8.x4.shared.b16 {%0,%1,%2,%3}, [%4];"
        : "=r"(r[0]), "=r"(r[1]), "=r"(r[2]), "=r"(r[3]) : "r"(addr));
}
__device__ __forceinline__ void ldsm_x2(uint32_t (&r)[2], uint32_t addr) {
    asm volatile("ldmatrix.sync.aligned.m8n8.x2.shared.b16 {%0,%1}, [%2];"
        : "=r"(r[0]), "=r"(r[1]) : "r"(addr));
}
__device__ __forceinline__ void mma_bf16(float (&d)[4], const uint32_t (&a)[4],
                                         const uint32_t (&b)[2]) {
    asm volatile(
        "mma.sync.aligned.m16n8k16.row.col.f32.bf16.bf16.f32 "
        "{%0,%1,%2,%3}, {%4,%5,%6,%7}, {%8,%9}, {%0,%1,%2,%3};"
        : "+f"(d[0]), "+f"(d[1]), "+f"(d[2]), "+f"(d[3])
        : "r"(a[0]), "r"(a[1]), "r"(a[2]), "r"(a[3]), "r"(b[0]), "r"(b[1]));
}
__device__ __forceinline__ void mma_f16(float (&d)[4], const uint32_t (&a)[4],
                                        const uint32_t (&b)[2]) {
    asm volatile(
        "mma.sync.aligned.m16n8k16.row.col.f32.f16.f16.f32 "
        "{%0,%1,%2,%3}, {%4,%5,%6,%7}, {%8,%9}, {%0,%1,%2,%3};"
        : "+f"(d[0]), "+f"(d[1]), "+f"(d[2]), "+f"(d[3])
        : "r"(a[0]), "r"(a[1]), "r"(a[2]), "r"(a[3]), "r"(b[0]), "r"(b[1]));
}

// ========================= scratch globals =================================
__device__ float g_img [ICH * NPTS];
__device__ float g_Lq  [LCH * NPTS];
__device__ float g_keys[HEADS * LCH * NPTS];
__device__ float g_t   [LCH * NPTS];
__device__ float g_wmap[HEADS * NPTS];
__device__ float g_spart[8][HEADS][NPTS];

// fp16 operands for keys + L_query GEMMs (single-pass)
__device__ __half g_wK_h [HEADS * LCH * ICH];
__device__ __half g_wL_h [LCH * LCH];
__device__ __half g_imgT_h[NPTS * ICH];
__device__ __half g_pfT_h [NPTS * LCH];

// bf16 split operands for fusion GEMM (3-term, high accuracy into output)
__device__ __nv_bfloat16 g_wF_hi[LCH * LCH],  g_wF_lo[LCH * LCH];
__device__ __nv_bfloat16 g_tT_hi[NPTS * LCH], g_tT_lo[NPTS * LCH];

// ========================= gather (prep inlined) ===========================
__global__ void gather_bev(const float* __restrict__ bev, const float* __restrict__ kp) {
    int n = blockIdx.x * blockDim.x + threadIdx.x;
    int c = blockIdx.y;
    float x = kp[n * 4 + 1] * 256.0f;
    float y = kp[n * 4 + 2] * 256.0f;
    int fx = (int)floorf(x);
    int fy = (int)floorf(y);
    int x0 = min(max(fx,     0), HWD - 1);
    int x1 = min(max(fx + 1, 0), HWD - 1);
    int y0 = min(max(fy,     0), HWD - 1);
    int y1 = min(max(fy + 1, 0), HWD - 1);
    float x0f = (float)x0, x1f = (float)x1, y0f = (float)y0, y1f = (float)y1;
    float wa = (x1f - x) * (y1f - y);
    float wb = (x1f - x) * (y - y0f);
    float wc = (x - x0f) * (y1f - y);
    float wd = (x - x0f) * (y - y0f);
    const float* pl = bev + (size_t)c * (HWD * HWD);
    float v = wa * pl[y0 * HWD + x0]
            + wb * pl[y1 * HWD + x0]
            + wc * pl[y0 * HWD + x1]
            + wd * pl[y1 * HWD + x1];
    g_img[(size_t)c * NPTS + n] = v;
}

// ========================= converts ========================================
// wK, wL -> fp16; wF -> bf16 hi/lo (for fusion)
__global__ void cvt_weights(const float* __restrict__ wK, const float* __restrict__ wL,
                            const float* __restrict__ wF) {
    int i = blockIdx.x * blockDim.x + threadIdx.x;
    const int CK = HEADS * LCH * ICH;
    const int CL = LCH * LCH;
    if (i < CK) {
        g_wK_h[i] = __float2half(wK[i]);
    } else if (i < CK + CL) {
        int j = i - CK;
        g_wL_h[j] = __float2half(wL[j]);
    } else if (i < CK + 2 * CL) {
        int j = i - CK - CL;
        float v = wF[j];
        __nv_bfloat16 h = __float2bfloat16(v);
        g_wF_hi[j] = h;
        g_wF_lo[j] = __float2bfloat16(v - __bfloat162float(h));
    }
}

// pf (K=512) and img (K=1024) -> fp16, transposed [N][K]
__global__ __launch_bounds__(256)
void cvt_acts(const float* __restrict__ pf) {
    __shared__ float tile[32][33];
    const float* src; __half* hT; int K, k0;
    if (blockIdx.y < 16) { src = pf;    hT = g_pfT_h;  K = LCH; k0 = blockIdx.y * 32; }
    else                 { src = g_img; hT = g_imgT_h; K = ICH; k0 = (blockIdx.y - 16) * 32; }
    int n0 = blockIdx.x * 32;
    int tx = threadIdx.x & 31;
    int ty = threadIdx.x >> 5;
    #pragma unroll
    for (int j = 0; j < 4; j++) {
        int k = k0 + ty + j * 8;
        tile[ty + j * 8][tx] = src[(size_t)k * NPTS + n0 + tx];
    }
    __syncthreads();
    #pragma unroll
    for (int j = 0; j < 4; j++) {
        int n = n0 + ty + j * 8;
        hT[(size_t)n * K + k0 + tx] = __float2half(tile[tx][ty + j * 8]);
    }
}

// t -> bf16 hi/lo transposed (for fusion bf16x3)
__global__ __launch_bounds__(256)
void cvt_split_T(const float* __restrict__ src,
                 __nv_bfloat16* __restrict__ hiT,
                 __nv_bfloat16* __restrict__ loT, int K, int N) {
    __shared__ float tile[32][33];
    int n0 = blockIdx.x * 32;
    int k0 = blockIdx.y * 32;
    int tx = threadIdx.x & 31;
    int ty = threadIdx.x >> 5;
    #pragma unroll
    for (int j = 0; j < 4; j++) {
        int k = k0 + ty + j * 8;
        tile[ty + j * 8][tx] = src[(size_t)k * N + n0 + tx];
    }
    __syncthreads();
    #pragma unroll
    for (int j = 0; j < 4; j++) {
        int n = n0 + ty + j * 8;
        float v = tile[tx][ty + j * 8];
        __nv_bfloat16 h = __float2bfloat16(v);
        hiT[(size_t)n * K + k0 + tx] = h;
        loT[(size_t)n * K + k0 + tx] = __float2bfloat16(v - __bfloat162float(h));
    }
}

// ================= fp16 single-pass GEMM (keys + L_query) ==================
// CTA tile 128x128, K-chunk 64, 3-stage cp.async ring, 1 barrier/chunk.
#define H_RSB    144                   // 128B data + 16B pad (conflict-free ldsm)
#define H_TILEB  (128 * H_RSB)         // 18432
#define H_STAGEB (2 * H_TILEB)         // A + B = 36864
#define H_NSTAGE 3
#define H_SMEM   (H_NSTAGE * H_STAGEB) // 110592

__device__ __forceinline__
void gemm16_body(const __half* __restrict__ A, const __half* __restrict__ B,
                 const float* __restrict__ bias, float* __restrict__ C,
                 int bm, int bn, int N, int K) {
    extern __shared__ char smem[];
    uint32_t sb = smem_to_u32(smem);

    int tid = threadIdx.x;
    int lane = tid & 31, wid = tid >> 5;
    int warp_m = wid & 1;           // 64-row slab
    int warp_n = wid >> 1;          // 32-col slab

    uint32_t aOff[4], bOff[2];
    #pragma unroll
    for (int mi = 0; mi < 4; mi++) {
        int row = warp_m * 64 + mi * 16 + (lane & 15);
        aOff[mi] = (uint32_t)(row * H_RSB + (lane >> 4) * 16);
    }
    #pragma unroll
    for (int nj = 0; nj < 2; nj++) {
        int row = warp_n * 32 + nj * 16 + ((lane >> 4) * 8) + (lane & 7);
        bOff[nj] = (uint32_t)(row * H_RSB + ((lane >> 3) & 1) * 16);
    }

    float acc[4][4][4];
    #pragma unroll
    for (int mi = 0; mi < 4; mi++)
        #pragma unroll
        for (int ni = 0; ni < 4; ni++)
            #pragma unroll
            for (int j = 0; j < 4; j++) acc[mi][ni][j] = 0.0f;

    // loader: 128 rows x 128B per tile; 2 threads/row, 4x16B each
    int ldRow = tid >> 1;
    int ldCol = (tid & 1) * 32;          // element offset (fp16)
    uint32_t ldSo = (uint32_t)(ldRow * H_RSB + (tid & 1) * 64);
    int nchunks = K >> 6;

    auto load_stage = [&](int stage, int k0) {
        uint32_t s = sb + stage * H_STAGEB;
        const __half* gA = A + (size_t)(bm + ldRow) * K + k0 + ldCol;
        const __half* gB = B + (size_t)(bn + ldRow) * K + k0 + ldCol;
        #pragma unroll
        for (int q = 0; q < 4; q++) {
            cp_async16(s + ldSo + q * 16, gA + q * 8);
            cp_async16(s + H_TILEB + ldSo + q * 16, gB + q * 8);
        }
    };

    load_stage(0, 0);
    CP_ASYNC_COMMIT();
    load_stage(1, 64);
    CP_ASYNC_COMMIT();

    int stage = 0;
    for (int c = 0; c < nchunks; c++) {
        if (c + 1 < nchunks) { CP_ASYNC_WAIT(1); } else { CP_ASYNC_WAIT(0); }
        __syncthreads();

        if (c + 2 < nchunks) {
            int ns = stage + 2; if (ns >= H_NSTAGE) ns -= H_NSTAGE;
            load_stage(ns, (c + 2) << 6);
            CP_ASYNC_COMMIT();
        }

        uint32_t sA = sb + stage * H_STAGEB;
        uint32_t sB = sA + H_TILEB;

        #pragma unroll
        for (int ks = 0; ks < 4; ks++) {
            uint32_t ko = ks * 32;      // 16 fp16 = 32 bytes
            uint32_t a[4][4], b[4][2];
            #pragma unroll
            for (int mi = 0; mi < 4; mi++) ldsm_x4(a[mi], sA + aOff[mi] + ko);
            #pragma unroll
            for (int nj = 0; nj < 2; nj++) {
                uint32_t t4[4];
                ldsm_x4(t4, sB + bOff[nj] + ko);
                b[2 * nj][0] = t4[0]; b[2 * nj][1] = t4[1];
                b[2 * nj + 1][0] = t4[2]; b[2 * nj + 1][1] = t4[3];
            }
            #pragma unroll
            for (int mi = 0; mi < 4; mi++)
                #pragma unroll
                for (int ni = 0; ni < 4; ni++) mma_f16(acc[mi][ni], a[mi], b[ni]);
        }
        stage++; if (stage >= H_NSTAGE) stage = 0;
    }

    int lr = lane >> 2, lc = (lane & 3) * 2;
    int r0 = bm + warp_m * 64;
    int c0 = bn + warp_n * 32;
    #pragma unroll
    for (int mi = 0; mi < 4; mi++) {
        int m1 = r0 + mi * 16 + lr;
        int m2 = m1 + 8;
        float bv1 = bias[m1];
        float bv2 = bias[m2];
        #pragma unroll
        for (int ni = 0; ni < 4; ni++) {
            int n = c0 + ni * 8 + lc;
            float2 v1 = make_float2(acc[mi][ni][0] + bv1, acc[mi][ni][1] + bv1);
            float2 v2 = make_float2(acc[mi][ni][2] + bv2, acc[mi][ni][3] + bv2);
            *(float2*)(C + (size_t)m1 * N + n) = v1;
            *(float2*)(C + (size_t)m2 * N + n) = v2;
        }
    }
}

// blocks [0,512) -> keys (M=2048,K=1024); [512,640) -> L_query (M=512,K=512)
__global__ __launch_bounds__(256, 2)
void gemm_dual16(const float* __restrict__ convLb, const float* __restrict__ imgHb) {
    const __half *A, *B;
    const float* bias;
    float* C;
    int bm, bn, K;
    int b = blockIdx.x;
    if (b < 512) {
        A = g_wK_h; B = g_imgT_h; bias = imgHb; C = g_keys; K = ICH;
        bm = (b >> 5) * 128; bn = (b & 31) * 128;
    } else {
        int j = b - 512;
        A = g_wL_h; B = g_pfT_h; bias = convLb; C = g_Lq; K = LCH;
        bm = (j >> 5) * 128; bn = (j & 31) * 128;
    }
    gemm16_body(A, B, bias, C, bm, bn, NPTS, K);
}

// ================= bf16x3 GEMM (fusion only; proven R9 design) =============
#define RSB   80
#define TILEB (128 * RSB)
#define STAGEB (4 * TILEB)
#define GEMM_SMEM (2 * STAGEB)        // 81920

__global__ __launch_bounds__(256, 2)
void gemm_single(const __nv_bfloat16* __restrict__ Ahi, const __nv_bfloat16* __restrict__ Alo,
                 const __nv_bfloat16* __restrict__ Bhi, const __nv_bfloat16* __restrict__ Blo,
                 const float* __restrict__ bias, float* __restrict__ C, int N, int K) {
    extern __shared__ char smem[];
    uint32_t sb = smem_to_u32(smem);

    int tid = threadIdx.x;
    int lane = tid & 31, wid = tid >> 5;
    int warp_m = wid & 1;
    int warp_n = wid >> 1;
    int bm = blockIdx.y * 128;
    int bn = blockIdx.x * 128;

    uint32_t aOff[4], bOff[4];
    #pragma unroll
    for (int mi = 0; mi < 4; mi++) {
        int row = warp_m * 64 + mi * 16 + (lane & 15);
        aOff[mi] = (uint32_t)(row * RSB + (lane >> 4) * 16);
    }
    #pragma unroll
    for (int ni = 0; ni < 4; ni++) {
        int row = warp_n * 32 + ni * 8 + (lane & 7);
        bOff[ni] = (uint32_t)(row * RSB + ((lane >> 3) & 1) * 16);
    }

    float acc[4][4][4];
    #pragma unroll
    for (int mi = 0; mi < 4; mi++)
        #pragma unroll
        for (int ni = 0; ni < 4; ni++)
            #pragma unroll
            for (int j = 0; j < 4; j++) acc[mi][ni][j] = 0.0f;

    int ldRow0 = tid >> 2;
    int ldSeg  = tid & 3;
    int nchunks = K >> 5;

    auto load_stage = [&](int stage, int k0) {
        uint32_t s = sb + stage * STAGEB;
        #pragma unroll
        for (int it = 0; it < 2; it++) {
            int row = ldRow0 + it * 64;
            uint32_t so = (uint32_t)(row * RSB + ldSeg * 16);
            size_t goA = (size_t)(bm + row) * K + k0 + ldSeg * 8;
            size_t goB = (size_t)(bn + row) * K + k0 + ldSeg * 8;
            cp_async16(s + 0 * TILEB + so, Ahi + goA);
            cp_async16(s + 1 * TILEB + so, Alo + goA);
            cp_async16(s + 2 * TILEB + so, Bhi + goB);
            cp_async16(s + 3 * TILEB + so, Blo + goB);
        }
    };

    load_stage(0, 0);
    CP_ASYNC_COMMIT();

    for (int c = 0; c < nchunks; c++) {
        if (c + 1 < nchunks) {
            load_stage((c + 1) & 1, (c + 1) << 5);
            CP_ASYNC_COMMIT();
            CP_ASYNC_WAIT(1);
        } else {
            CP_ASYNC_WAIT(0);
        }
        __syncthreads();

        uint32_t s = sb + (c & 1) * STAGEB;
        uint32_t sAh = s, sAl = s + TILEB, sBh = s + 2 * TILEB, sBl = s + 3 * TILEB;

        #pragma unroll
        for (int ks = 0; ks < 2; ks++) {
            uint32_t ko = ks * 32;
            uint32_t a[4][4], bh[4][2], bl[4][2];
            #pragma unroll
            for (int mi = 0; mi < 4; mi++) ldsm_x4(a[mi], sAh + aOff[mi] + ko);
            #pragma unroll
            for (int ni = 0; ni < 4; ni++) ldsm_x2(bh[ni], sBh + bOff[ni] + ko);
            #pragma unroll
            for (int ni = 0; ni < 4; ni++) ldsm_x2(bl[ni], sBl + bOff[ni] + ko);
            #pragma unroll
            for (int mi = 0; mi < 4; mi++)
                #pragma unroll
                for (int ni = 0; ni < 4; ni++) mma_bf16(acc[mi][ni], a[mi], bh[ni]);
            #pragma unroll
            for (int mi = 0; mi < 4; mi++)
                #pragma unroll
                for (int ni = 0; ni < 4; ni++) mma_bf16(acc[mi][ni], a[mi], bl[ni]);
            #pragma unroll
            for (int mi = 0; mi < 4; mi++) ldsm_x4(a[mi], sAl + aOff[mi] + ko);
            #pragma unroll
            for (int mi = 0; mi < 4; mi++)
                #pragma unroll
                for (int ni = 0; ni < 4; ni++) mma_bf16(acc[mi][ni], a[mi], bh[ni]);
        }
        __syncthreads();
    }

    int lr = lane >> 2, lc = (lane & 3) * 2;
    int r0 = bm + warp_m * 64;
    int c0 = bn + warp_n * 32;
    #pragma unroll
    for (int mi = 0; mi < 4; mi++) {
        int m1 = r0 + mi * 16 + lr;
        int m2 = m1 + 8;
        float bv1 = bias[m1];
        float bv2 = bias[m2];
        #pragma unroll
        for (int ni = 0; ni < 4; ni++) {
            int n = c0 + ni * 8 + lc;
            float2 v1 = make_float2(acc[mi][ni][0] + bv1, acc[mi][ni][1] + bv1);
            float2 v2 = make_float2(acc[mi][ni][2] + bv2, acc[mi][ni][3] + bv2);
            *(float2*)(C + (size_t)m1 * N + n) = v1;
            *(float2*)(C + (size_t)m2 * N + n) = v2;
        }
    }
}

// ========================= attention tail ==================================
__global__ void score_part() {
    int n = blockIdx.x * blockDim.x + threadIdx.x;
    int l0 = blockIdx.y * 64;
    float a0 = 0.f, a1 = 0.f, a2 = 0.f, a3 = 0.f;
    for (int l = l0; l < l0 + 64; l++) {
        float lq = g_Lq[l * NPTS + n];
        a0 += g_keys[(0 * LCH + l) * NPTS + n] * lq;
        a1 += g_keys[(1 * LCH + l) * NPTS + n] * lq;
        a2 += g_keys[(2 * LCH + l) * NPTS + n] * lq;
        a3 += g_keys[(3 * LCH + l) * NPTS + n] * lq;
    }
    g_spart[blockIdx.y][0][n] = a0;
    g_spart[blockIdx.y][1][n] = a1;
    g_spart[blockIdx.y][2][n] = a2;
    g_spart[blockIdx.y][3][n] = a3;
}

__global__ void softmax_k() {
    int n = blockIdx.x * blockDim.x + threadIdx.x;
    float a0 = 0.f, a1 = 0.f, a2 = 0.f, a3 = 0.f;
    #pragma unroll
    for (int p = 0; p < 8; p++) {
        a0 += g_spart[p][0][n];
        a1 += g_spart[p][1][n];
        a2 += g_spart[p][2][n];
        a3 += g_spart[p][3][n];
    }
    const float inv = 0.04419417382415922f;  // 1/sqrt(512)
    a0 *= inv; a1 *= inv; a2 *= inv; a3 *= inv;
    float m = fmaxf(fmaxf(a0, a1), fmaxf(a2, a3));
    float e0 = expf(a0 - m), e1 = expf(a1 - m), e2 = expf(a2 - m), e3 = expf(a3 - m);
    float s = e0 + e1 + e2 + e3;
    g_wmap[0 * NPTS + n] = e0 / s;
    g_wmap[1 * NPTS + n] = e1 / s;
    g_wmap[2 * NPTS + n] = e2 / s;
    g_wmap[3 * NPTS + n] = e3 / s;
}

__global__ void compute_t() {
    size_t i = (size_t)blockIdx.x * blockDim.x + threadIdx.x;
    int n = (int)(i & (NPTS - 1));
    float w0 = g_wmap[0 * NPTS + n];
    float w1 = g_wmap[1 * NPTS + n];
    float w2 = g_wmap[2 * NPTS + n];
    float w3 = g_wmap[3 * NPTS + n];
    const size_t HS = (size_t)LCH * NPTS;
    float z = w0 * g_keys[i] + w1 * g_keys[HS + i]
            + w2 * g_keys[2 * HS + i] + w3 * g_keys[3 * HS + i];
    g_t[i] = z + g_Lq[i];
}

__global__ __launch_bounds__(256)
void layernorm(const float* __restrict__ lnw, const float* __restrict__ lnb) {
    int l = blockIdx.x;
    float* row = g_t + (size_t)l * NPTS;
    float s = 0.f, ss = 0.f;
    for (int n = threadIdx.x; n < NPTS; n += 256) {
        float v = row[n];
        s += v; ss += v * v;
    }
    __shared__ float rs[8], rss[8];
    for (int o = 16; o > 0; o >>= 1) {
        s  += __shfl_down_sync(0xffffffffu, s,  o);
        ss += __shfl_down_sync(0xffffffffu, ss, o);
    }
    int wid = threadIdx.x >> 5, lid = threadIdx.x & 31;
    if (lid == 0) { rs[wid] = s; rss[wid] = ss; }
    __syncthreads();
    if (wid == 0) {
        s  = (lid < 8) ? rs[lid]  : 0.f;
        ss = (lid < 8) ? rss[lid] : 0.f;
        for (int o = 4; o > 0; o >>= 1) {
            s  += __shfl_down_sync(0xffffffffu, s,  o);
            ss += __shfl_down_sync(0xffffffffu, ss, o);
        }
        if (lid == 0) { rs[0] = s; rss[0] = ss; }
    }
    __syncthreads();
    float mu = rs[0] * (1.0f / NPTS);
    float var = rss[0] * (1.0f / NPTS) - mu * mu;
    float rstd = rsqrtf(var + 1e-5f);
    for (int n = threadIdx.x; n < NPTS; n += 256)
        row[n] = (row[n] - mu) * rstd * lnw[n] + lnb[n];
}

__global__ void copy_wmap(float* __restrict__ out) {
    int i = blockIdx.x * blockDim.x + threadIdx.x;
    if (i < HEADS * NPTS) out[i] = g_wmap[i];
}

// ========================= launch ==========================================
extern "C" void kernel_launch(void* const* d_in, const int* in_sizes, int n_in,
                              void* d_out, int out_size) {
    const float* point_features = (const float*)d_in[0];
    const float* keypoints      = (const float*)d_in[1];
    const float* bev_features   = (const float*)d_in[2];
    const float* conv_L_w       = (const float*)d_in[3];
    const float* conv_L_b       = (const float*)d_in[4];
    const float* img_head_w     = (const float*)d_in[5];
    const float* img_head_b     = (const float*)d_in[6];
    const float* ln_w           = (const float*)d_in[7];
    const float* ln_b           = (const float*)d_in[8];
    const float* conv_fusion_w  = (const float*)d_in[9];
    const float* conv_fusion_b  = (const float*)d_in[10];
    float* out = (float*)d_out;

    cudaFuncSetAttribute(gemm_dual16, cudaFuncAttributeMaxDynamicSharedMemorySize, H_SMEM);
    cudaFuncSetAttribute(gemm_single, cudaFuncAttributeMaxDynamicSharedMemorySize, GEMM_SMEM);

    float *p_t;
    cudaGetSymbolAddress((void**)&p_t, g_t);
    __nv_bfloat16 *wFh, *wFl, *tTh, *tTl;
    cudaGetSymbolAddress((void**)&wFh, g_wF_hi);  cudaGetSymbolAddress((void**)&wFl, g_wF_lo);
    cudaGetSymbolAddress((void**)&tTh, g_tT_hi);  cudaGetSymbolAddress((void**)&tTl, g_tT_lo);

    // 1) BEV gather
    gather_bev<<<dim3(NPTS / 256, ICH), 256>>>(bev_features, keypoints);
    // 2) weight converts (wK,wL fp16; wF bf16 hi/lo)
    {
        int count = HEADS * LCH * ICH + 2 * LCH * LCH;
        cvt_weights<<<(count + 255) / 256, 256>>>(img_head_w, conv_L_w, conv_fusion_w);
    }
    // 3) pf + img transpose -> fp16
    cvt_acts<<<dim3(NPTS / 32, 48), 256>>>(point_features);
    // 4) keys + L_query fp16 GEMMs  (profiled slot #4)
    gemm_dual16<<<640, 256, H_SMEM>>>(conv_L_b, img_head_b);
    // 5) partial scores
    score_part<<<dim3(NPTS / 256, 8), 256>>>();
    // 6) softmax over heads
    softmax_k<<<NPTS / 256, 256>>>();
    // 7) t = z + L_query
    compute_t<<<(LCH * NPTS) / 256, 256>>>();
    // 8) LayerNorm over point axis
    layernorm<<<LCH, 256>>>(ln_w, ln_b);
    // 9) t transpose/split (bf16 hi/lo)
    cvt_split_T<<<dim3(NPTS / 32, LCH / 32), 256>>>(p_t, tTh, tTl, LCH, NPTS);
    // 10) fusion GEMM (bf16x3, high accuracy) -> out
    gemm_single<<<dim3(NPTS / 128, LCH / 128), 256, GEMM_SMEM>>>(
        wFh, wFl, tTh, tTl, conv_fusion_b, out, NPTS, LCH);
    // 11) weightmap tail
    if (out_size >= LCH * NPTS + HEADS * NPTS) {
        copy_wmap<<<(HEADS * NPTS + 255) / 256, 256>>>(out + (size_t)LCH * NPTS);
    }
}

// round 12
// speedup vs baseline: 1.6051x; 1.0228x over previous
#include <cuda_runtime.h>
#include <cuda_bf16.h>
#include <cuda_fp16.h>
#include <math.h>
#include <cstdint>

#define NPTS 4096
#define LCH  512
#define ICH  1024
#define HWD  256
#define HEADS 4

// ========================= helpers =========================================
__device__ __forceinline__ uint32_t smem_to_u32(const void* smem_ptr) {
    uint32_t addr;
    asm("{ .reg .u64 tmp; cvta.to.shared.u64 tmp, %1; cvt.u32.u64 %0, tmp; }"
        : "=r"(addr) : "l"(smem_ptr));
    return addr;
}
__device__ __forceinline__ void cp_async16(uint32_t dst_smem, const void* src) {
    asm volatile("cp.async.cg.shared.global [%0], [%1], 16;"
        :: "r"(dst_smem), "l"((unsigned long long)__cvta_generic_to_global(src)) : "memory");
}
#define CP_ASYNC_COMMIT() asm volatile("cp.async.commit_group;" ::: "memory")
#define CP_ASYNC_WAIT(n)  asm volatile("cp.async.wait_group %0;" :: "n"(n) : "memory")

__device__ __forceinline__ void ldsm_x4(uint32_t (&r)[4], uint32_t addr) {
    asm volatile("ldmatrix.sync.aligned.m8n8.x4.shared.b16 {%0,%1,%2,%3}, [%4];"
        : "=r"(r[0]), "=r"(r[1]), "=r"(r[2]), "=r"(r[3]) : "r"(addr));
}
__device__ __forceinline__ void mma_f16(float (&d)[4], const uint32_t (&a)[4],
                                        const uint32_t (&b)[2]) {
    asm volatile(
        "mma.sync.aligned.m16n8k16.row.col.f32.f16.f16.f32 "
        "{%0,%1,%2,%3}, {%4,%5,%6,%7}, {%8,%9}, {%0,%1,%2,%3};"
        : "+f"(d[0]), "+f"(d[1]), "+f"(d[2]), "+f"(d[3])
        : "r"(a[0]), "r"(a[1]), "r"(a[2]), "r"(a[3]), "r"(b[0]), "r"(b[1]));
}

// ========================= scratch globals =================================
__device__ float g_Lq  [LCH * NPTS];
__device__ float g_keys[HEADS * LCH * NPTS];
__device__ float g_t   [LCH * NPTS];
__device__ float g_wmap[HEADS * NPTS];
__device__ float g_spart[8][HEADS][NPTS];

__device__ __half g_wK_h [HEADS * LCH * ICH];
__device__ __half g_wL_h [LCH * LCH];
__device__ __half g_wF_h [LCH * LCH];
__device__ __half g_imgT_h[NPTS * ICH];
__device__ __half g_pfT_h [NPTS * LCH];
__device__ __half g_tT_h  [NPTS * LCH];

// ========== gather: bilinear + transpose + fp16 convert in one pass ========
__global__ __launch_bounds__(256)
void gather_bevT(const float* __restrict__ bev, const float* __restrict__ kp) {
    __shared__ float tile[32][33];   // [c_local][n_local]
    int n0 = blockIdx.x * 32;
    int c0 = blockIdx.y * 32;
    int tx = threadIdx.x & 31;
    int ty = threadIdx.x >> 5;

    int n = n0 + tx;
    float x = kp[n * 4 + 1] * 256.0f;
    float y = kp[n * 4 + 2] * 256.0f;
    int fx = (int)floorf(x);
    int fy = (int)floorf(y);
    int x0 = min(max(fx,     0), HWD - 1);
    int x1 = min(max(fx + 1, 0), HWD - 1);
    int y0 = min(max(fy,     0), HWD - 1);
    int y1 = min(max(fy + 1, 0), HWD - 1);
    float x0f = (float)x0, x1f = (float)x1, y0f = (float)y0, y1f = (float)y1;
    float wa = (x1f - x) * (y1f - y);
    float wb = (x1f - x) * (y - y0f);
    float wc = (x - x0f) * (y1f - y);
    float wd = (x - x0f) * (y - y0f);
    int oa = y0 * HWD + x0, ob = y1 * HWD + x0, oc = y0 * HWD + x1, od = y1 * HWD + x1;

    #pragma unroll
    for (int j = 0; j < 4; j++) {
        int c = c0 + ty + j * 8;
        const float* pl = bev + (size_t)c * (HWD * HWD);
        tile[ty + j * 8][tx] = wa * pl[oa] + wb * pl[ob] + wc * pl[oc] + wd * pl[od];
    }
    __syncthreads();
    #pragma unroll
    for (int j = 0; j < 4; j++) {
        int nn = n0 + ty + j * 8;
        g_imgT_h[(size_t)nn * ICH + c0 + tx] = __float2half(tile[tx][ty + j * 8]);
    }
}

// ========================= converts ========================================
__global__ void cvt_weights(const float* __restrict__ wK, const float* __restrict__ wL,
                            const float* __restrict__ wF) {
    int i = blockIdx.x * blockDim.x + threadIdx.x;
    const int CK = HEADS * LCH * ICH;
    const int CL = LCH * LCH;
    if (i < CK) {
        g_wK_h[i] = __float2half(wK[i]);
    } else if (i < CK + CL) {
        int j = i - CK;
        g_wL_h[j] = __float2half(wL[j]);
    } else if (i < CK + 2 * CL) {
        int j = i - CK - CL;
        g_wF_h[j] = __float2half(wF[j]);
    }
}

// fp32 [K][NPTS] -> fp16 [NPTS][K]; grid (NPTS/32, K/32)
__global__ __launch_bounds__(256)
void cvt_T16(const float* __restrict__ src, __half* __restrict__ dst, int K) {
    __shared__ float tile[32][33];
    int n0 = blockIdx.x * 32;
    int k0 = blockIdx.y * 32;
    int tx = threadIdx.x & 31;
    int ty = threadIdx.x >> 5;
    #pragma unroll
    for (int j = 0; j < 4; j++) {
        int k = k0 + ty + j * 8;
        tile[ty + j * 8][tx] = src[(size_t)k * NPTS + n0 + tx];
    }
    __syncthreads();
    #pragma unroll
    for (int j = 0; j < 4; j++) {
        int n = n0 + ty + j * 8;
        dst[(size_t)n * K + k0 + tx] = __float2half(tile[tx][ty + j * 8]);
    }
}

// ================= fp16 single-pass GEMM body (proven R11) =================
#define H_RSB    144
#define H_TILEB  (128 * H_RSB)
#define H_STAGEB (2 * H_TILEB)
#define H_NSTAGE 3
#define H_SMEM   (H_NSTAGE * H_STAGEB) // 110592

__device__ __forceinline__
void gemm16_body(const __half* __restrict__ A, const __half* __restrict__ B,
                 const float* __restrict__ bias, float* __restrict__ C,
                 int bm, int bn, int N, int K) {
    extern __shared__ char smem[];
    uint32_t sb = smem_to_u32(smem);

    int tid = threadIdx.x;
    int lane = tid & 31, wid = tid >> 5;
    int warp_m = wid & 1;
    int warp_n = wid >> 1;

    uint32_t aOff[4], bOff[2];
    #pragma unroll
    for (int mi = 0; mi < 4; mi++) {
        int row = warp_m * 64 + mi * 16 + (lane & 15);
        aOff[mi] = (uint32_t)(row * H_RSB + (lane >> 4) * 16);
    }
    #pragma unroll
    for (int nj = 0; nj < 2; nj++) {
        int row = warp_n * 32 + nj * 16 + ((lane >> 4) * 8) + (lane & 7);
        bOff[nj] = (uint32_t)(row * H_RSB + ((lane >> 3) & 1) * 16);
    }

    float acc[4][4][4];
    #pragma unroll
    for (int mi = 0; mi < 4; mi++)
        #pragma unroll
        for (int ni = 0; ni < 4; ni++)
            #pragma unroll
            for (int j = 0; j < 4; j++) acc[mi][ni][j] = 0.0f;

    int ldRow = tid >> 1;
    int ldCol = (tid & 1) * 32;
    uint32_t ldSo = (uint32_t)(ldRow * H_RSB + (tid & 1) * 64);
    int nchunks = K >> 6;

    auto load_stage = [&](int stage, int k0) {
        uint32_t s = sb + stage * H_STAGEB;
        const __half* gA = A + (size_t)(bm + ldRow) * K + k0 + ldCol;
        const __half* gB = B + (size_t)(bn + ldRow) * K + k0 + ldCol;
        #pragma unroll
        for (int q = 0; q < 4; q++) {
            cp_async16(s + ldSo + q * 16, gA + q * 8);
            cp_async16(s + H_TILEB + ldSo + q * 16, gB + q * 8);
        }
    };

    load_stage(0, 0);
    CP_ASYNC_COMMIT();
    load_stage(1, 64);
    CP_ASYNC_COMMIT();

    int stage = 0;
    for (int c = 0; c < nchunks; c++) {
        if (c + 1 < nchunks) { CP_ASYNC_WAIT(1); } else { CP_ASYNC_WAIT(0); }
        __syncthreads();

        if (c + 2 < nchunks) {
            int ns = stage + 2; if (ns >= H_NSTAGE) ns -= H_NSTAGE;
            load_stage(ns, (c + 2) << 6);
            CP_ASYNC_COMMIT();
        }

        uint32_t sA = sb + stage * H_STAGEB;
        uint32_t sB = sA + H_TILEB;

        #pragma unroll
        for (int ks = 0; ks < 4; ks++) {
            uint32_t ko = ks * 32;
            uint32_t a[4][4], b[4][2];
            #pragma unroll
            for (int mi = 0; mi < 4; mi++) ldsm_x4(a[mi], sA + aOff[mi] + ko);
            #pragma unroll
            for (int nj = 0; nj < 2; nj++) {
                uint32_t t4[4];
                ldsm_x4(t4, sB + bOff[nj] + ko);
                b[2 * nj][0] = t4[0]; b[2 * nj][1] = t4[1];
                b[2 * nj + 1][0] = t4[2]; b[2 * nj + 1][1] = t4[3];
            }
            #pragma unroll
            for (int mi = 0; mi < 4; mi++)
                #pragma unroll
                for (int ni = 0; ni < 4; ni++) mma_f16(acc[mi][ni], a[mi], b[ni]);
        }
        stage++; if (stage >= H_NSTAGE) stage = 0;
    }

    int lr = lane >> 2, lc = (lane & 3) * 2;
    int r0 = bm + warp_m * 64;
    int c0 = bn + warp_n * 32;
    #pragma unroll
    for (int mi = 0; mi < 4; mi++) {
        int m1 = r0 + mi * 16 + lr;
        int m2 = m1 + 8;
        float bv1 = bias[m1];
        float bv2 = bias[m2];
        #pragma unroll
        for (int ni = 0; ni < 4; ni++) {
            int n = c0 + ni * 8 + lc;
            float2 v1 = make_float2(acc[mi][ni][0] + bv1, acc[mi][ni][1] + bv1);
            float2 v2 = make_float2(acc[mi][ni][2] + bv2, acc[mi][ni][3] + bv2);
            *(float2*)(C + (size_t)m1 * N + n) = v1;
            *(float2*)(C + (size_t)m2 * N + n) = v2;
        }
    }
}

__global__ __launch_bounds__(256, 2)
void gemm_dual16(const float* __restrict__ convLb, const float* __restrict__ imgHb) {
    const __half *A, *B;
    const float* bias;
    float* C;
    int bm, bn, K;
    int b = blockIdx.x;
    if (b < 512) {
        A = g_wK_h; B = g_imgT_h; bias = imgHb; C = g_keys; K = ICH;
        bm = (b >> 5) * 128; bn = (b & 31) * 128;
    } else {
        int j = b - 512;
        A = g_wL_h; B = g_pfT_h; bias = convLb; C = g_Lq; K = LCH;
        bm = (j >> 5) * 128; bn = (j & 31) * 128;
    }
    gemm16_body(A, B, bias, C, bm, bn, NPTS, K);
}

__global__ __launch_bounds__(256, 2)
void gemm_single16(const __half* __restrict__ A, const __half* __restrict__ B,
                   const float* __restrict__ bias, float* __restrict__ C, int N, int K) {
    gemm16_body(A, B, bias, C, blockIdx.y * 128, blockIdx.x * 128, N, K);
}

// ========================= attention tail ==================================
__global__ void score_part() {
    int n = blockIdx.x * blockDim.x + threadIdx.x;
    int l0 = blockIdx.y * 64;
    float a0 = 0.f, a1 = 0.f, a2 = 0.f, a3 = 0.f;
    for (int l = l0; l < l0 + 64; l++) {
        float lq = g_Lq[l * NPTS + n];
        a0 += g_keys[(0 * LCH + l) * NPTS + n] * lq;
        a1 += g_keys[(1 * LCH + l) * NPTS + n] * lq;
        a2 += g_keys[(2 * LCH + l) * NPTS + n] * lq;
        a3 += g_keys[(3 * LCH + l) * NPTS + n] * lq;
    }
    g_spart[blockIdx.y][0][n] = a0;
    g_spart[blockIdx.y][1][n] = a1;
    g_spart[blockIdx.y][2][n] = a2;
    g_spart[blockIdx.y][3][n] = a3;
}

__global__ void softmax_k() {
    int n = blockIdx.x * blockDim.x + threadIdx.x;
    float a0 = 0.f, a1 = 0.f, a2 = 0.f, a3 = 0.f;
    #pragma unroll
    for (int p = 0; p < 8; p++) {
        a0 += g_spart[p][0][n];
        a1 += g_spart[p][1][n];
        a2 += g_spart[p][2][n];
        a3 += g_spart[p][3][n];
    }
    const float inv = 0.04419417382415922f;  // 1/sqrt(512)
    a0 *= inv; a1 *= inv; a2 *= inv; a3 *= inv;
    float m = fmaxf(fmaxf(a0, a1), fmaxf(a2, a3));
    float e0 = expf(a0 - m), e1 = expf(a1 - m), e2 = expf(a2 - m), e3 = expf(a3 - m);
    float s = e0 + e1 + e2 + e3;
    g_wmap[0 * NPTS + n] = e0 / s;
    g_wmap[1 * NPTS + n] = e1 / s;
    g_wmap[2 * NPTS + n] = e2 / s;
    g_wmap[3 * NPTS + n] = e3 / s;
}

// fused t = z + Lq and LayerNorm over the point axis; one block per channel l
__global__ __launch_bounds__(256)
void layernorm_fused(const float* __restrict__ lnw, const float* __restrict__ lnb) {
    __shared__ float tbuf[NPTS];
    __shared__ float rs[8], rss[8];
    int l = blockIdx.x;
    const size_t HS = (size_t)LCH * NPTS;
    const float* k0p = g_keys + (size_t)l * NPTS;
    const float* lqp = g_Lq + (size_t)l * NPTS;
    float s = 0.f, ss = 0.f;
    for (int n = threadIdx.x; n < NPTS; n += 256) {
        float w0 = g_wmap[0 * NPTS + n];
        float w1 = g_wmap[1 * NPTS + n];
        float w2 = g_wmap[2 * NPTS + n];
        float w3 = g_wmap[3 * NPTS + n];
        float z = w0 * k0p[n] + w1 * k0p[HS + n]
                + w2 * k0p[2 * HS + n] + w3 * k0p[3 * HS + n];
        float t = z + lqp[n];
        tbuf[n] = t;
        s += t; ss += t * t;
    }
    for (int o = 16; o > 0; o >>= 1) {
        s  += __shfl_down_sync(0xffffffffu, s,  o);
        ss += __shfl_down_sync(0xffffffffu, ss, o);
    }
    int wid = threadIdx.x >> 5, lid = threadIdx.x & 31;
    if (lid == 0) { rs[wid] = s; rss[wid] = ss; }
    __syncthreads();
    if (wid == 0) {
        s  = (lid < 8) ? rs[lid]  : 0.f;
        ss = (lid < 8) ? rss[lid] : 0.f;
        for (int o = 4; o > 0; o >>= 1) {
            s  += __shfl_down_sync(0xffffffffu, s,  o);
            ss += __shfl_down_sync(0xffffffffu, ss, o);
        }
        if (lid == 0) { rs[0] = s; rss[0] = ss; }
    }
    __syncthreads();
    float mu = rs[0] * (1.0f / NPTS);
    float var = rss[0] * (1.0f / NPTS) - mu * mu;
    float rstd = rsqrtf(var + 1e-5f);
    float* row = g_t + (size_t)l * NPTS;
    for (int n = threadIdx.x; n < NPTS; n += 256)
        row[n] = (tbuf[n] - mu) * rstd * lnw[n] + lnb[n];
}

__global__ void copy_wmap(float* __restrict__ out) {
    int i = blockIdx.x * blockDim.x + threadIdx.x;
    if (i < HEADS * NPTS) out[i] = g_wmap[i];
}

// ========================= launch ==========================================
extern "C" void kernel_launch(void* const* d_in, const int* in_sizes, int n_in,
                              void* d_out, int out_size) {
    const float* point_features = (const float*)d_in[0];
    const float* keypoints      = (const float*)d_in[1];
    const float* bev_features   = (const float*)d_in[2];
    const float* conv_L_b       = (const float*)d_in[4];
    const float* conv_L_w       = (const float*)d_in[3];
    const float* img_head_w     = (const float*)d_in[5];
    const float* img_head_b     = (const float*)d_in[6];
    const float* ln_w           = (const float*)d_in[7];
    const float* ln_b           = (const float*)d_in[8];
    const float* conv_fusion_w  = (const float*)d_in[9];
    const float* conv_fusion_b  = (const float*)d_in[10];
    float* out = (float*)d_out;

    cudaFuncSetAttribute(gemm_dual16,   cudaFuncAttributeMaxDynamicSharedMemorySize, H_SMEM);
    cudaFuncSetAttribute(gemm_single16, cudaFuncAttributeMaxDynamicSharedMemorySize, H_SMEM);

    float* p_t;
    cudaGetSymbolAddress((void**)&p_t, g_t);
    __half *wFh, *tTh, *pfTh;
    cudaGetSymbolAddress((void**)&wFh,  g_wF_h);
    cudaGetSymbolAddress((void**)&tTh,  g_tT_h);
    cudaGetSymbolAddress((void**)&pfTh, g_pfT_h);

    // 1) BEV gather -> fp16 transposed directly (g_img eliminated)
    gather_bevT<<<dim3(NPTS / 32, ICH / 32), 256>>>(bev_features, keypoints);
    // 2) weight converts (all fp16)
    {
        int count = HEADS * LCH * ICH + 2 * LCH * LCH;
        cvt_weights<<<(count + 255) / 256, 256>>>(img_head_w, conv_L_w, conv_fusion_w);
    }
    // 3) pf transpose -> fp16
    cvt_T16<<<dim3(NPTS / 32, LCH / 32), 256>>>(point_features, pfTh, LCH);
    // 4) keys + L_query fp16 GEMMs  (profiled slot #4)
    gemm_dual16<<<640, 256, H_SMEM>>>(conv_L_b, img_head_b);
    // 5) partial scores
    score_part<<<dim3(NPTS / 256, 8), 256>>>();
    // 6) softmax over heads
    softmax_k<<<NPTS / 256, 256>>>();
    // 7) fused t + LayerNorm
    layernorm_fused<<<LCH, 256>>>(ln_w, ln_b);
    // 8) t transpose -> fp16
    cvt_T16<<<dim3(NPTS / 32, LCH / 32), 256>>>(p_t, tTh, LCH);
    // 9) fusion GEMM (fp16) -> out
    gemm_single16<<<dim3(NPTS / 128, LCH / 128), 256, H_SMEM>>>(
        wFh, tTh, conv_fusion_b, out, NPTS, LCH);
    // 10) weightmap tail
    if (out_size >= LCH * NPTS + HEADS * NPTS) {
        copy_wmap<<<(HEADS * NPTS + 255) / 256, 256>>>(out + (size_t)LCH * NPTS);
    }
}

// round 13
// speedup vs baseline: 1.6683x; 1.0394x over previous
#include <cuda_runtime.h>
#include <cuda_bf16.h>
#include <cuda_fp16.h>
#include <math.h>
#include <cstdint>

#define NPTS 4096
#define LCH  512
#define ICH  1024
#define HWD  256
#define HEADS 4

// ========================= helpers =========================================
__device__ __forceinline__ uint32_t smem_to_u32(const void* smem_ptr) {
    uint32_t addr;
    asm("{ .reg .u64 tmp; cvta.to.shared.u64 tmp, %1; cvt.u32.u64 %0, tmp; }"
        : "=r"(addr) : "l"(smem_ptr));
    return addr;
}
__device__ __forceinline__ void cp_async16(uint32_t dst_smem, const void* src) {
    asm volatile("cp.async.cg.shared.global [%0], [%1], 16;"
        :: "r"(dst_smem), "l"((unsigned long long)__cvta_generic_to_global(src)) : "memory");
}
#define CP_ASYNC_COMMIT() asm volatile("cp.async.commit_group;" ::: "memory")
#define CP_ASYNC_WAIT(n)  asm volatile("cp.async.wait_group %0;" :: "n"(n) : "memory")

__device__ __forceinline__ void ldsm_x4(uint32_t (&r)[4], uint32_t addr) {
    asm volatile("ldmatrix.sync.aligned.m8n8.x4.shared.b16 {%0,%1,%2,%3}, [%4];"
        : "=r"(r[0]), "=r"(r[1]), "=r"(r[2]), "=r"(r[3]) : "r"(addr));
}
__device__ __forceinline__ void mma_f16(float (&d)[4], const uint32_t (&a)[4],
                                        const uint32_t (&b)[2]) {
    asm volatile(
        "mma.sync.aligned.m16n8k16.row.col.f32.f16.f16.f32 "
        "{%0,%1,%2,%3}, {%4,%5,%6,%7}, {%8,%9}, {%0,%1,%2,%3};"
        : "+f"(d[0]), "+f"(d[1]), "+f"(d[2]), "+f"(d[3])
        : "r"(a[0]), "r"(a[1]), "r"(a[2]), "r"(a[3]), "r"(b[0]), "r"(b[1]));
}

// ========================= scratch globals =================================
__device__ __half g_Lq_h  [LCH * NPTS];            // fp16 L_query
__device__ __half g_keys_h[HEADS * LCH * NPTS];    // fp16 keys
__device__ float  g_t   [LCH * NPTS];
__device__ float  g_wmap[HEADS * NPTS];
__device__ float  g_spart[16][HEADS][NPTS];        // partial scores (32-wide l chunks)

__device__ __half g_wK_h [HEADS * LCH * ICH];
__device__ __half g_wL_h [LCH * LCH];
__device__ __half g_wF_h [LCH * LCH];
__device__ __half g_imgT_h[NPTS * ICH];
__device__ __half g_pfT_h [NPTS * LCH];
__device__ __half g_tT_h  [NPTS * LCH];

// ========== gather: bilinear + transpose + fp16 convert in one pass ========
__global__ __launch_bounds__(256)
void gather_bevT(const float* __restrict__ bev, const float* __restrict__ kp) {
    __shared__ float tile[32][33];   // [c_local][n_local]
    int n0 = blockIdx.x * 32;
    int c0 = blockIdx.y * 32;
    int tx = threadIdx.x & 31;
    int ty = threadIdx.x >> 5;

    int n = n0 + tx;
    float x = kp[n * 4 + 1] * 256.0f;
    float y = kp[n * 4 + 2] * 256.0f;
    int fx = (int)floorf(x);
    int fy = (int)floorf(y);
    int x0 = min(max(fx,     0), HWD - 1);
    int x1 = min(max(fx + 1, 0), HWD - 1);
    int y0 = min(max(fy,     0), HWD - 1);
    int y1 = min(max(fy + 1, 0), HWD - 1);
    float x0f = (float)x0, x1f = (float)x1, y0f = (float)y0, y1f = (float)y1;
    float wa = (x1f - x) * (y1f - y);
    float wb = (x1f - x) * (y - y0f);
    float wc = (x - x0f) * (y1f - y);
    float wd = (x - x0f) * (y - y0f);
    int oa = y0 * HWD + x0, ob = y1 * HWD + x0, oc = y0 * HWD + x1, od = y1 * HWD + x1;

    #pragma unroll
    for (int j = 0; j < 4; j++) {
        int c = c0 + ty + j * 8;
        const float* pl = bev + (size_t)c * (HWD * HWD);
        tile[ty + j * 8][tx] = wa * pl[oa] + wb * pl[ob] + wc * pl[oc] + wd * pl[od];
    }
    __syncthreads();
    #pragma unroll
    for (int j = 0; j < 4; j++) {
        int nn = n0 + ty + j * 8;
        g_imgT_h[(size_t)nn * ICH + c0 + tx] = __float2half(tile[tx][ty + j * 8]);
    }
}

// ========================= converts ========================================
__global__ void cvt_weights(const float* __restrict__ wK, const float* __restrict__ wL,
                            const float* __restrict__ wF) {
    int i = blockIdx.x * blockDim.x + threadIdx.x;
    const int CK = HEADS * LCH * ICH;
    const int CL = LCH * LCH;
    if (i < CK) {
        g_wK_h[i] = __float2half(wK[i]);
    } else if (i < CK + CL) {
        int j = i - CK;
        g_wL_h[j] = __float2half(wL[j]);
    } else if (i < CK + 2 * CL) {
        int j = i - CK - CL;
        g_wF_h[j] = __float2half(wF[j]);
    }
}

// fp32 [K][NPTS] -> fp16 [NPTS][K]; grid (NPTS/32, K/32)
__global__ __launch_bounds__(256)
void cvt_T16(const float* __restrict__ src, __half* __restrict__ dst, int K) {
    __shared__ float tile[32][33];
    int n0 = blockIdx.x * 32;
    int k0 = blockIdx.y * 32;
    int tx = threadIdx.x & 31;
    int ty = threadIdx.x >> 5;
    #pragma unroll
    for (int j = 0; j < 4; j++) {
        int k = k0 + ty + j * 8;
        tile[ty + j * 8][tx] = src[(size_t)k * NPTS + n0 + tx];
    }
    __syncthreads();
    #pragma unroll
    for (int j = 0; j < 4; j++) {
        int n = n0 + ty + j * 8;
        dst[(size_t)n * K + k0 + tx] = __float2half(tile[tx][ty + j * 8]);
    }
}

// ================= fp16 GEMM body, templated output type ==================
#define H_RSB    144
#define H_TILEB  (128 * H_RSB)
#define H_STAGEB (2 * H_TILEB)
#define H_NSTAGE 3
#define H_SMEM   (H_NSTAGE * H_STAGEB) // 110592

template <typename OutT>
__device__ __forceinline__
void gemm16_body(const __half* __restrict__ A, const __half* __restrict__ B,
                 const float* __restrict__ bias, OutT* __restrict__ C,
                 int bm, int bn, int N, int K) {
    extern __shared__ char smem[];
    uint32_t sb = smem_to_u32(smem);

    int tid = threadIdx.x;
    int lane = tid & 31, wid = tid >> 5;
    int warp_m = wid & 1;
    int warp_n = wid >> 1;

    uint32_t aOff[4], bOff[2];
    #pragma unroll
    for (int mi = 0; mi < 4; mi++) {
        int row = warp_m * 64 + mi * 16 + (lane & 15);
        aOff[mi] = (uint32_t)(row * H_RSB + (lane >> 4) * 16);
    }
    #pragma unroll
    for (int nj = 0; nj < 2; nj++) {
        int row = warp_n * 32 + nj * 16 + ((lane >> 4) * 8) + (lane & 7);
        bOff[nj] = (uint32_t)(row * H_RSB + ((lane >> 3) & 1) * 16);
    }

    float acc[4][4][4];
    #pragma unroll
    for (int mi = 0; mi < 4; mi++)
        #pragma unroll
        for (int ni = 0; ni < 4; ni++)
            #pragma unroll
            for (int j = 0; j < 4; j++) acc[mi][ni][j] = 0.0f;

    int ldRow = tid >> 1;
    int ldCol = (tid & 1) * 32;
    uint32_t ldSo = (uint32_t)(ldRow * H_RSB + (tid & 1) * 64);
    int nchunks = K >> 6;

    auto load_stage = [&](int stage, int k0) {
        uint32_t s = sb + stage * H_STAGEB;
        const __half* gA = A + (size_t)(bm + ldRow) * K + k0 + ldCol;
        const __half* gB = B + (size_t)(bn + ldRow) * K + k0 + ldCol;
        #pragma unroll
        for (int q = 0; q < 4; q++) {
            cp_async16(s + ldSo + q * 16, gA + q * 8);
            cp_async16(s + H_TILEB + ldSo + q * 16, gB + q * 8);
        }
    };

    load_stage(0, 0);
    CP_ASYNC_COMMIT();
    load_stage(1, 64);
    CP_ASYNC_COMMIT();

    int stage = 0;
    for (int c = 0; c < nchunks; c++) {
        if (c + 1 < nchunks) { CP_ASYNC_WAIT(1); } else { CP_ASYNC_WAIT(0); }
        __syncthreads();

        if (c + 2 < nchunks) {
            int ns = stage + 2; if (ns >= H_NSTAGE) ns -= H_NSTAGE;
            load_stage(ns, (c + 2) << 6);
            CP_ASYNC_COMMIT();
        }

        uint32_t sA = sb + stage * H_STAGEB;
        uint32_t sB = sA + H_TILEB;

        #pragma unroll
        for (int ks = 0; ks < 4; ks++) {
            uint32_t ko = ks * 32;
            uint32_t a[4][4], b[4][2];
            #pragma unroll
            for (int mi = 0; mi < 4; mi++) ldsm_x4(a[mi], sA + aOff[mi] + ko);
            #pragma unroll
            for (int nj = 0; nj < 2; nj++) {
                uint32_t t4[4];
                ldsm_x4(t4, sB + bOff[nj] + ko);
                b[2 * nj][0] = t4[0]; b[2 * nj][1] = t4[1];
                b[2 * nj + 1][0] = t4[2]; b[2 * nj + 1][1] = t4[3];
            }
            #pragma unroll
            for (int mi = 0; mi < 4; mi++)
                #pragma unroll
                for (int ni = 0; ni < 4; ni++) mma_f16(acc[mi][ni], a[mi], b[ni]);
        }
        stage++; if (stage >= H_NSTAGE) stage = 0;
    }

    int lr = lane >> 2, lc = (lane & 3) * 2;
    int r0 = bm + warp_m * 64;
    int c0 = bn + warp_n * 32;
    #pragma unroll
    for (int mi = 0; mi < 4; mi++) {
        int m1 = r0 + mi * 16 + lr;
        int m2 = m1 + 8;
        float bv1 = bias[m1];
        float bv2 = bias[m2];
        #pragma unroll
        for (int ni = 0; ni < 4; ni++) {
            int n = c0 + ni * 8 + lc;
            if constexpr (sizeof(OutT) == 2) {
                __half2 h1 = __floats2half2_rn(acc[mi][ni][0] + bv1, acc[mi][ni][1] + bv1);
                __half2 h2 = __floats2half2_rn(acc[mi][ni][2] + bv2, acc[mi][ni][3] + bv2);
                *(__half2*)((__half*)C + (size_t)m1 * N + n) = h1;
                *(__half2*)((__half*)C + (size_t)m2 * N + n) = h2;
            } else {
                float2 v1 = make_float2(acc[mi][ni][0] + bv1, acc[mi][ni][1] + bv1);
                float2 v2 = make_float2(acc[mi][ni][2] + bv2, acc[mi][ni][3] + bv2);
                *(float2*)((float*)C + (size_t)m1 * N + n) = v1;
                *(float2*)((float*)C + (size_t)m2 * N + n) = v2;
            }
        }
    }
}

// blocks [0,512) -> keys (fp16 out); [512,640) -> L_query (fp16 out)
__global__ __launch_bounds__(256, 2)
void gemm_dual16(const float* __restrict__ convLb, const float* __restrict__ imgHb) {
    const __half *A, *B;
    const float* bias;
    __half* C;
    int bm, bn, K;
    int b = blockIdx.x;
    if (b < 512) {
        A = g_wK_h; B = g_imgT_h; bias = imgHb; C = g_keys_h; K = ICH;
        bm = (b >> 5) * 128; bn = (b & 31) * 128;
    } else {
        int j = b - 512;
        A = g_wL_h; B = g_pfT_h; bias = convLb; C = g_Lq_h; K = LCH;
        bm = (j >> 5) * 128; bn = (j & 31) * 128;
    }
    gemm16_body<__half>(A, B, bias, C, bm, bn, NPTS, K);
}

__global__ __launch_bounds__(256, 2)
void gemm_single16(const __half* __restrict__ A, const __half* __restrict__ B,
                   const float* __restrict__ bias, float* __restrict__ C, int N, int K) {
    gemm16_body<float>(A, B, bias, C, blockIdx.y * 128, blockIdx.x * 128, N, K);
}

// ========================= attention tail ==================================
// partial scores over 32-wide l-chunks; grid (8, 16); half2 loads
__global__ void score_part() {
    int n2 = blockIdx.x * blockDim.x + threadIdx.x;   // 0..2047 (pairs of n)
    int l0 = blockIdx.y * 32;
    const __half2* keys2 = (const __half2*)g_keys_h;
    const __half2* lq2   = (const __half2*)g_Lq_h;
    const int NP2 = NPTS / 2;
    float2 a[HEADS];
    #pragma unroll
    for (int h = 0; h < HEADS; h++) a[h] = make_float2(0.f, 0.f);
    for (int l = l0; l < l0 + 32; l++) {
        float2 lq = __half22float2(lq2[l * NP2 + n2]);
        #pragma unroll
        for (int h = 0; h < HEADS; h++) {
            float2 k = __half22float2(keys2[(size_t)(h * LCH + l) * NP2 + n2]);
            a[h].x += k.x * lq.x;
            a[h].y += k.y * lq.y;
        }
    }
    #pragma unroll
    for (int h = 0; h < HEADS; h++) {
        g_spart[blockIdx.y][h][2 * n2]     = a[h].x;
        g_spart[blockIdx.y][h][2 * n2 + 1] = a[h].y;
    }
}

__global__ void softmax_k() {
    int n = blockIdx.x * blockDim.x + threadIdx.x;
    float a0 = 0.f, a1 = 0.f, a2 = 0.f, a3 = 0.f;
    #pragma unroll
    for (int p = 0; p < 16; p++) {
        a0 += g_spart[p][0][n];
        a1 += g_spart[p][1][n];
        a2 += g_spart[p][2][n];
        a3 += g_spart[p][3][n];
    }
    const float inv = 0.04419417382415922f;  // 1/sqrt(512)
    a0 *= inv; a1 *= inv; a2 *= inv; a3 *= inv;
    float m = fmaxf(fmaxf(a0, a1), fmaxf(a2, a3));
    float e0 = expf(a0 - m), e1 = expf(a1 - m), e2 = expf(a2 - m), e3 = expf(a3 - m);
    float s = e0 + e1 + e2 + e3;
    g_wmap[0 * NPTS + n] = e0 / s;
    g_wmap[1 * NPTS + n] = e1 / s;
    g_wmap[2 * NPTS + n] = e2 / s;
    g_wmap[3 * NPTS + n] = e3 / s;
}

// fused t = z + Lq and LayerNorm; one block per channel l; half2 reads
__global__ __launch_bounds__(256)
void layernorm_fused(const float* __restrict__ lnw, const float* __restrict__ lnb) {
    __shared__ float tbuf[NPTS];
    __shared__ float rs[8], rss[8];
    int l = blockIdx.x;
    const int NP2 = NPTS / 2;
    const size_t HS2 = (size_t)LCH * NP2;
    const __half2* k2  = (const __half2*)g_keys_h + (size_t)l * NP2;
    const __half2* lq2 = (const __half2*)g_Lq_h + (size_t)l * NP2;
    const float2* wm2  = (const float2*)g_wmap;
    float s = 0.f, ss = 0.f;
    for (int n2 = threadIdx.x; n2 < NP2; n2 += 256) {
        float2 w0 = wm2[0 * NP2 + n2];
        float2 w1 = wm2[1 * NP2 + n2];
        float2 w2 = wm2[2 * NP2 + n2];
        float2 w3 = wm2[3 * NP2 + n2];
        float2 k0 = __half22float2(k2[n2]);
        float2 k1 = __half22float2(k2[HS2 + n2]);
        float2 kk2 = __half22float2(k2[2 * HS2 + n2]);
        float2 k3 = __half22float2(k2[3 * HS2 + n2]);
        float2 lq = __half22float2(lq2[n2]);
        float tx = w0.x * k0.x + w1.x * k1.x + w2.x * kk2.x + w3.x * k3.x + lq.x;
        float ty = w0.y * k0.y + w1.y * k1.y + w2.y * kk2.y + w3.y * k3.y + lq.y;
        tbuf[2 * n2]     = tx;
        tbuf[2 * n2 + 1] = ty;
        s += tx + ty;
        ss += tx * tx + ty * ty;
    }
    for (int o = 16; o > 0; o >>= 1) {
        s  += __shfl_down_sync(0xffffffffu, s,  o);
        ss += __shfl_down_sync(0xffffffffu, ss, o);
    }
    int wid = threadIdx.x >> 5, lid = threadIdx.x & 31;
    if (lid == 0) { rs[wid] = s; rss[wid] = ss; }
    __syncthreads();
    if (wid == 0) {
        s  = (lid < 8) ? rs[lid]  : 0.f;
        ss = (lid < 8) ? rss[lid] : 0.f;
        for (int o = 4; o > 0; o >>= 1) {
            s  += __shfl_down_sync(0xffffffffu, s,  o);
            ss += __shfl_down_sync(0xffffffffu, ss, o);
        }
        if (lid == 0) { rs[0] = s; rss[0] = ss; }
    }
    __syncthreads();
    float mu = rs[0] * (1.0f / NPTS);
    float var = rss[0] * (1.0f / NPTS) - mu * mu;
    float rstd = rsqrtf(var + 1e-5f);
    float* row = g_t + (size_t)l * NPTS;
    for (int n = threadIdx.x; n < NPTS; n += 256)
        row[n] = (tbuf[n] - mu) * rstd * lnw[n] + lnb[n];
}

__global__ void copy_wmap(float* __restrict__ out) {
    int i = blockIdx.x * blockDim.x + threadIdx.x;
    if (i < HEADS * NPTS) out[i] = g_wmap[i];
}

// ========================= launch ==========================================
extern "C" void kernel_launch(void* const* d_in, const int* in_sizes, int n_in,
                              void* d_out, int out_size) {
    const float* point_features = (const float*)d_in[0];
    const float* keypoints      = (const float*)d_in[1];
    const float* bev_features   = (const float*)d_in[2];
    const float* conv_L_w       = (const float*)d_in[3];
    const float* conv_L_b       = (const float*)d_in[4];
    const float* img_head_w     = (const float*)d_in[5];
    const float* img_head_b     = (const float*)d_in[6];
    const float* ln_w           = (const float*)d_in[7];
    const float* ln_b           = (const float*)d_in[8];
    const float* conv_fusion_w  = (const float*)d_in[9];
    const float* conv_fusion_b  = (const float*)d_in[10];
    float* out = (float*)d_out;

    cudaFuncSetAttribute(gemm_dual16,   cudaFuncAttributeMaxDynamicSharedMemorySize, H_SMEM);
    cudaFuncSetAttribute(gemm_single16, cudaFuncAttributeMaxDynamicSharedMemorySize, H_SMEM);

    float* p_t;
    cudaGetSymbolAddress((void**)&p_t, g_t);
    __half *wFh, *tTh, *pfTh;
    cudaGetSymbolAddress((void**)&wFh,  g_wF_h);
    cudaGetSymbolAddress((void**)&tTh,  g_tT_h);
    cudaGetSymbolAddress((void**)&pfTh, g_pfT_h);

    // 1) BEV gather -> fp16 transposed directly
    gather_bevT<<<dim3(NPTS / 32, ICH / 32), 256>>>(bev_features, keypoints);
    // 2) weight converts (all fp16)
    {
        int count = HEADS * LCH * ICH + 2 * LCH * LCH;
        cvt_weights<<<(count + 255) / 256, 256>>>(img_head_w, conv_L_w, conv_fusion_w);
    }
    // 3) pf transpose -> fp16
    cvt_T16<<<dim3(NPTS / 32, LCH / 32), 256>>>(point_features, pfTh, LCH);
    // 4) keys + L_query fp16 GEMMs, fp16 outputs  (profiled slot #4)
    gemm_dual16<<<640, 256, H_SMEM>>>(conv_L_b, img_head_b);
    // 5) partial scores (128 CTAs, half2 loads)
    score_part<<<dim3(NPTS / 512, 16), 256>>>();
    // 6) softmax over heads
    softmax_k<<<NPTS / 256, 256>>>();
    // 7) fused t + LayerNorm (half2 loads)
    layernorm_fused<<<LCH, 256>>>(ln_w, ln_b);
    // 8) t transpose -> fp16
    cvt_T16<<<dim3(NPTS / 32, LCH / 32), 256>>>(p_t, tTh, LCH);
    // 9) fusion GEMM (fp16 in, fp32 out) -> out
    gemm_single16<<<dim3(NPTS / 128, LCH / 128), 256, H_SMEM>>>(
        wFh, tTh, conv_fusion_b, out, NPTS, LCH);
    // 10) weightmap tail
    if (out_size >= LCH * NPTS + HEADS * NPTS) {
        copy_wmap<<<(HEADS * NPTS + 255) / 256, 256>>>(out + (size_t)LCH * NPTS);
    }
}

// round 14
// speedup vs baseline: 1.9245x; 1.1535x over previous
#include <cuda_runtime.h>
#include <cuda_bf16.h>
#include <cuda_fp16.h>
#include <math.h>
#include <cstdint>

#define NPTS 4096
#define LCH  512
#define ICH  1024
#define HWD  256
#define HEADS 4

// ========================= helpers =========================================
__device__ __forceinline__ uint32_t smem_to_u32(const void* smem_ptr) {
    uint32_t addr;
    asm("{ .reg .u64 tmp; cvta.to.shared.u64 tmp, %1; cvt.u32.u64 %0, tmp; }"
        : "=r"(addr) : "l"(smem_ptr));
    return addr;
}
__device__ __forceinline__ void cp_async16(uint32_t dst_smem, const void* src) {
    asm volatile("cp.async.cg.shared.global [%0], [%1], 16;"
        :: "r"(dst_smem), "l"((unsigned long long)__cvta_generic_to_global(src)) : "memory");
}
#define CP_ASYNC_COMMIT() asm volatile("cp.async.commit_group;" ::: "memory")
#define CP_ASYNC_WAIT(n)  asm volatile("cp.async.wait_group %0;" :: "n"(n) : "memory")

__device__ __forceinline__ void ldsm_x4(uint32_t (&r)[4], uint32_t addr) {
    asm volatile("ldmatrix.sync.aligned.m8n8.x4.shared.b16 {%0,%1,%2,%3}, [%4];"
        : "=r"(r[0]), "=r"(r[1]), "=r"(r[2]), "=r"(r[3]) : "r"(addr));
}
__device__ __forceinline__ void mma_f16(float (&d)[4], const uint32_t (&a)[4],
                                        const uint32_t (&b)[2]) {
    asm volatile(
        "mma.sync.aligned.m16n8k16.row.col.f32.f16.f16.f32 "
        "{%0,%1,%2,%3}, {%4,%5,%6,%7}, {%8,%9}, {%0,%1,%2,%3};"
        : "+f"(d[0]), "+f"(d[1]), "+f"(d[2]), "+f"(d[3])
        : "r"(a[0]), "r"(a[1]), "r"(a[2]), "r"(a[3]), "r"(b[0]), "r"(b[1]));
}

// ========================= scratch globals =================================
__device__ __half g_Lq_h  [LCH * NPTS];
__device__ __half g_keys_h[HEADS * LCH * NPTS];
__device__ float  g_t   [LCH * NPTS];
__device__ float  g_wmap[HEADS * NPTS];
__device__ float  g_spart[16][HEADS][NPTS];

__device__ __half g_wK_h [HEADS * LCH * ICH];
__device__ __half g_wL_h [LCH * LCH];
__device__ __half g_wF_h [LCH * LCH];
__device__ __half g_imgT_h[NPTS * ICH];
__device__ __half g_pfT_h [NPTS * LCH];
__device__ __half g_tT_h  [NPTS * LCH];

// ========== gather: bilinear + transpose + fp16 convert in one pass ========
__global__ __launch_bounds__(256)
void gather_bevT(const float* __restrict__ bev, const float* __restrict__ kp) {
    __shared__ float tile[32][33];
    int n0 = blockIdx.x * 32;
    int c0 = blockIdx.y * 32;
    int tx = threadIdx.x & 31;
    int ty = threadIdx.x >> 5;

    int n = n0 + tx;
    float x = kp[n * 4 + 1] * 256.0f;
    float y = kp[n * 4 + 2] * 256.0f;
    int fx = (int)floorf(x);
    int fy = (int)floorf(y);
    int x0 = min(max(fx,     0), HWD - 1);
    int x1 = min(max(fx + 1, 0), HWD - 1);
    int y0 = min(max(fy,     0), HWD - 1);
    int y1 = min(max(fy + 1, 0), HWD - 1);
    float x0f = (float)x0, x1f = (float)x1, y0f = (float)y0, y1f = (float)y1;
    float wa = (x1f - x) * (y1f - y);
    float wb = (x1f - x) * (y - y0f);
    float wc = (x - x0f) * (y1f - y);
    float wd = (x - x0f) * (y - y0f);
    int oa = y0 * HWD + x0, ob = y1 * HWD + x0, oc = y0 * HWD + x1, od = y1 * HWD + x1;

    #pragma unroll
    for (int j = 0; j < 4; j++) {
        int c = c0 + ty + j * 8;
        const float* pl = bev + (size_t)c * (HWD * HWD);
        tile[ty + j * 8][tx] = wa * pl[oa] + wb * pl[ob] + wc * pl[oc] + wd * pl[od];
    }
    __syncthreads();
    #pragma unroll
    for (int j = 0; j < 4; j++) {
        int nn = n0 + ty + j * 8;
        g_imgT_h[(size_t)nn * ICH + c0 + tx] = __float2half(tile[tx][ty + j * 8]);
    }
}

// ========================= converts ========================================
__global__ void cvt_weights(const float* __restrict__ wK, const float* __restrict__ wL,
                            const float* __restrict__ wF) {
    int i = blockIdx.x * blockDim.x + threadIdx.x;
    const int CK = HEADS * LCH * ICH;
    const int CL = LCH * LCH;
    if (i < CK) {
        g_wK_h[i] = __float2half(wK[i]);
    } else if (i < CK + CL) {
        int j = i - CK;
        g_wL_h[j] = __float2half(wL[j]);
    } else if (i < CK + 2 * CL) {
        int j = i - CK - CL;
        g_wF_h[j] = __float2half(wF[j]);
    }
}

__global__ __launch_bounds__(256)
void cvt_T16(const float* __restrict__ src, __half* __restrict__ dst, int K) {
    __shared__ float tile[32][33];
    int n0 = blockIdx.x * 32;
    int k0 = blockIdx.y * 32;
    int tx = threadIdx.x & 31;
    int ty = threadIdx.x >> 5;
    #pragma unroll
    for (int j = 0; j < 4; j++) {
        int k = k0 + ty + j * 8;
        tile[ty + j * 8][tx] = src[(size_t)k * NPTS + n0 + tx];
    }
    __syncthreads();
    #pragma unroll
    for (int j = 0; j < 4; j++) {
        int n = n0 + ty + j * 8;
        dst[(size_t)n * K + k0 + tx] = __float2half(tile[tx][ty + j * 8]);
    }
}

// ============== dual GEMM: 256x128 tile, 512 threads, fp16 out =============
// Per-chunk LDGSTS/MAC is 0.75x of the 128x128 tiling (cp.async-issue bound).
#define D_RSB    144
#define D_ATILE  (256 * D_RSB)        // 36864
#define D_BTILE  (128 * D_RSB)        // 18432
#define D_STAGEB (D_ATILE + D_BTILE)  // 55296
#define D_NSTAGE 3
#define D_SMEM   (D_NSTAGE * D_STAGEB) // 165888

__global__ __launch_bounds__(512, 1)
void gemm_dual16(const float* __restrict__ convLb, const float* __restrict__ imgHb) {
    extern __shared__ char smem[];
    uint32_t sb = smem_to_u32(smem);

    const __half *A, *B;
    const float* bias;
    __half* C;
    int bm, bn, K;
    int b = blockIdx.x;
    if (b < 256) {
        A = g_wK_h; B = g_imgT_h; bias = imgHb; C = g_keys_h; K = ICH;
        bm = (b >> 5) * 256; bn = (b & 31) * 128;
    } else {
        int j = b - 256;
        A = g_wL_h; B = g_pfT_h; bias = convLb; C = g_Lq_h; K = LCH;
        bm = (j >> 5) * 256; bn = (j & 31) * 128;
    }

    int tid = threadIdx.x;
    int lane = tid & 31, wid = tid >> 5;
    int warp_m = wid & 3;            // 0..3 -> 64-row slab of 256
    int warp_n = wid >> 2;           // 0..3 -> 32-col slab of 128

    uint32_t aOff[4], bOff[2];
    #pragma unroll
    for (int mi = 0; mi < 4; mi++) {
        int row = warp_m * 64 + mi * 16 + (lane & 15);
        aOff[mi] = (uint32_t)(row * D_RSB + (lane >> 4) * 16);
    }
    #pragma unroll
    for (int nj = 0; nj < 2; nj++) {
        int row = warp_n * 32 + nj * 16 + ((lane >> 4) * 8) + (lane & 7);
        bOff[nj] = (uint32_t)(row * D_RSB + ((lane >> 3) & 1) * 16);
    }

    float acc[4][4][4];
    #pragma unroll
    for (int mi = 0; mi < 4; mi++)
        #pragma unroll
        for (int ni = 0; ni < 4; ni++)
            #pragma unroll
            for (int j = 0; j < 4; j++) acc[mi][ni][j] = 0.0f;

    // loader: A 2048 x 16B (4 iters of 512), B 1024 x 16B (2 iters)
    int nchunks = K >> 6;
    auto load_stage = [&](int stage, int k0) {
        uint32_t s = sb + stage * D_STAGEB;
        #pragma unroll
        for (int it = 0; it < 4; it++) {
            int id = it * 512 + tid;
            int row = id >> 3, seg = id & 7;
            cp_async16(s + (uint32_t)(row * D_RSB + seg * 16),
                       A + (size_t)(bm + row) * K + k0 + seg * 8);
        }
        #pragma unroll
        for (int it = 0; it < 2; it++) {
            int id = it * 512 + tid;
            int row = id >> 3, seg = id & 7;
            cp_async16(s + D_ATILE + (uint32_t)(row * D_RSB + seg * 16),
                       B + (size_t)(bn + row) * K + k0 + seg * 8);
        }
    };

    load_stage(0, 0);
    CP_ASYNC_COMMIT();
    load_stage(1, 64);
    CP_ASYNC_COMMIT();

    int stage = 0;
    for (int c = 0; c < nchunks; c++) {
        if (c + 1 < nchunks) { CP_ASYNC_WAIT(1); } else { CP_ASYNC_WAIT(0); }
        __syncthreads();

        if (c + 2 < nchunks) {
            int ns = stage + 2; if (ns >= D_NSTAGE) ns -= D_NSTAGE;
            load_stage(ns, (c + 2) << 6);
            CP_ASYNC_COMMIT();
        }

        uint32_t sA = sb + stage * D_STAGEB;
        uint32_t sB = sA + D_ATILE;

        #pragma unroll
        for (int ks = 0; ks < 4; ks++) {
            uint32_t ko = ks * 32;
            uint32_t a[4][4], b[4][2];
            #pragma unroll
            for (int mi = 0; mi < 4; mi++) ldsm_x4(a[mi], sA + aOff[mi] + ko);
            #pragma unroll
            for (int nj = 0; nj < 2; nj++) {
                uint32_t t4[4];
                ldsm_x4(t4, sB + bOff[nj] + ko);
                b[2 * nj][0] = t4[0]; b[2 * nj][1] = t4[1];
                b[2 * nj + 1][0] = t4[2]; b[2 * nj + 1][1] = t4[3];
            }
            #pragma unroll
            for (int mi = 0; mi < 4; mi++)
                #pragma unroll
                for (int ni = 0; ni < 4; ni++) mma_f16(acc[mi][ni], a[mi], b[ni]);
        }
        stage++; if (stage >= D_NSTAGE) stage = 0;
    }

    int lr = lane >> 2, lc = (lane & 3) * 2;
    int r0 = bm + warp_m * 64;
    int c0 = bn + warp_n * 32;
    #pragma unroll
    for (int mi = 0; mi < 4; mi++) {
        int m1 = r0 + mi * 16 + lr;
        int m2 = m1 + 8;
        float bv1 = bias[m1];
        float bv2 = bias[m2];
        #pragma unroll
        for (int ni = 0; ni < 4; ni++) {
            int n = c0 + ni * 8 + lc;
            __half2 h1 = __floats2half2_rn(acc[mi][ni][0] + bv1, acc[mi][ni][1] + bv1);
            __half2 h2 = __floats2half2_rn(acc[mi][ni][2] + bv2, acc[mi][ni][3] + bv2);
            *(__half2*)(C + (size_t)m1 * NPTS + n) = h1;
            *(__half2*)(C + (size_t)m2 * NPTS + n) = h2;
        }
    }
}

// ============ fusion GEMM: proven 128x128 / 256-thread body ================
#define H_RSB    144
#define H_TILEB  (128 * H_RSB)
#define H_STAGEB (2 * H_TILEB)
#define H_NSTAGE 3
#define H_SMEM   (H_NSTAGE * H_STAGEB) // 110592

__global__ __launch_bounds__(256, 2)
void gemm_single16(const __half* __restrict__ A, const __half* __restrict__ B,
                   const float* __restrict__ bias, float* __restrict__ C, int N, int K) {
    extern __shared__ char smem[];
    uint32_t sb = smem_to_u32(smem);
    int bm = blockIdx.y * 128;
    int bn = blockIdx.x * 128;

    int tid = threadIdx.x;
    int lane = tid & 31, wid = tid >> 5;
    int warp_m = wid & 1;
    int warp_n = wid >> 1;

    uint32_t aOff[4], bOff[2];
    #pragma unroll
    for (int mi = 0; mi < 4; mi++) {
        int row = warp_m * 64 + mi * 16 + (lane & 15);
        aOff[mi] = (uint32_t)(row * H_RSB + (lane >> 4) * 16);
    }
    #pragma unroll
    for (int nj = 0; nj < 2; nj++) {
        int row = warp_n * 32 + nj * 16 + ((lane >> 4) * 8) + (lane & 7);
        bOff[nj] = (uint32_t)(row * H_RSB + ((lane >> 3) & 1) * 16);
    }

    float acc[4][4][4];
    #pragma unroll
    for (int mi = 0; mi < 4; mi++)
        #pragma unroll
        for (int ni = 0; ni < 4; ni++)
            #pragma unroll
            for (int j = 0; j < 4; j++) acc[mi][ni][j] = 0.0f;

    int ldRow = tid >> 1;
    int ldCol = (tid & 1) * 32;
    uint32_t ldSo = (uint32_t)(ldRow * H_RSB + (tid & 1) * 64);
    int nchunks = K >> 6;

    auto load_stage = [&](int stage, int k0) {
        uint32_t s = sb + stage * H_STAGEB;
        const __half* gA = A + (size_t)(bm + ldRow) * K + k0 + ldCol;
        const __half* gB = B + (size_t)(bn + ldRow) * K + k0 + ldCol;
        #pragma unroll
        for (int q = 0; q < 4; q++) {
            cp_async16(s + ldSo + q * 16, gA + q * 8);
            cp_async16(s + H_TILEB + ldSo + q * 16, gB + q * 8);
        }
    };

    load_stage(0, 0);
    CP_ASYNC_COMMIT();
    load_stage(1, 64);
    CP_ASYNC_COMMIT();

    int stage = 0;
    for (int c = 0; c < nchunks; c++) {
        if (c + 1 < nchunks) { CP_ASYNC_WAIT(1); } else { CP_ASYNC_WAIT(0); }
        __syncthreads();

        if (c + 2 < nchunks) {
            int ns = stage + 2; if (ns >= H_NSTAGE) ns -= H_NSTAGE;
            load_stage(ns, (c + 2) << 6);
            CP_ASYNC_COMMIT();
        }

        uint32_t sA = sb + stage * H_STAGEB;
        uint32_t sB = sA + H_TILEB;

        #pragma unroll
        for (int ks = 0; ks < 4; ks++) {
            uint32_t ko = ks * 32;
            uint32_t a[4][4], b[4][2];
            #pragma unroll
            for (int mi = 0; mi < 4; mi++) ldsm_x4(a[mi], sA + aOff[mi] + ko);
            #pragma unroll
            for (int nj = 0; nj < 2; nj++) {
                uint32_t t4[4];
                ldsm_x4(t4, sB + bOff[nj] + ko);
                b[2 * nj][0] = t4[0]; b[2 * nj][1] = t4[1];
                b[2 * nj + 1][0] = t4[2]; b[2 * nj + 1][1] = t4[3];
            }
            #pragma unroll
            for (int mi = 0; mi < 4; mi++)
                #pragma unroll
                for (int ni = 0; ni < 4; ni++) mma_f16(acc[mi][ni], a[mi], b[ni]);
        }
        stage++; if (stage >= H_NSTAGE) stage = 0;
    }

    int lr = lane >> 2, lc = (lane & 3) * 2;
    int r0 = bm + warp_m * 64;
    int c0 = bn + warp_n * 32;
    #pragma unroll
    for (int mi = 0; mi < 4; mi++) {
        int m1 = r0 + mi * 16 + lr;
        int m2 = m1 + 8;
        float bv1 = bias[m1];
        float bv2 = bias[m2];
        #pragma unroll
        for (int ni = 0; ni < 4; ni++) {
            int n = c0 + ni * 8 + lc;
            float2 v1 = make_float2(acc[mi][ni][0] + bv1, acc[mi][ni][1] + bv1);
            float2 v2 = make_float2(acc[mi][ni][2] + bv2, acc[mi][ni][3] + bv2);
            *(float2*)(C + (size_t)m1 * N + n) = v1;
            *(float2*)(C + (size_t)m2 * N + n) = v2;
        }
    }
}

// ========================= attention tail ==================================
__global__ void score_part() {
    int n2 = blockIdx.x * blockDim.x + threadIdx.x;
    int l0 = blockIdx.y * 32;
    const __half2* keys2 = (const __half2*)g_keys_h;
    const __half2* lq2   = (const __half2*)g_Lq_h;
    const int NP2 = NPTS / 2;
    float2 a[HEADS];
    #pragma unroll
    for (int h = 0; h < HEADS; h++) a[h] = make_float2(0.f, 0.f);
    for (int l = l0; l < l0 + 32; l++) {
        float2 lq = __half22float2(lq2[l * NP2 + n2]);
        #pragma unroll
        for (int h = 0; h < HEADS; h++) {
            float2 k = __half22float2(keys2[(size_t)(h * LCH + l) * NP2 + n2]);
            a[h].x += k.x * lq.x;
            a[h].y += k.y * lq.y;
        }
    }
    #pragma unroll
    for (int h = 0; h < HEADS; h++) {
        g_spart[blockIdx.y][h][2 * n2]     = a[h].x;
        g_spart[blockIdx.y][h][2 * n2 + 1] = a[h].y;
    }
}

// softmax over heads; also writes weightmap output tail (if wout != nullptr)
__global__ void softmax_k(float* __restrict__ wout) {
    int n = blockIdx.x * blockDim.x + threadIdx.x;
    float a0 = 0.f, a1 = 0.f, a2 = 0.f, a3 = 0.f;
    #pragma unroll
    for (int p = 0; p < 16; p++) {
        a0 += g_spart[p][0][n];
        a1 += g_spart[p][1][n];
        a2 += g_spart[p][2][n];
        a3 += g_spart[p][3][n];
    }
    const float inv = 0.04419417382415922f;  // 1/sqrt(512)
    a0 *= inv; a1 *= inv; a2 *= inv; a3 *= inv;
    float m = fmaxf(fmaxf(a0, a1), fmaxf(a2, a3));
    float e0 = expf(a0 - m), e1 = expf(a1 - m), e2 = expf(a2 - m), e3 = expf(a3 - m);
    float s = e0 + e1 + e2 + e3;
    float w0 = e0 / s, w1 = e1 / s, w2 = e2 / s, w3 = e3 / s;
    g_wmap[0 * NPTS + n] = w0;
    g_wmap[1 * NPTS + n] = w1;
    g_wmap[2 * NPTS + n] = w2;
    g_wmap[3 * NPTS + n] = w3;
    if (wout) {
        wout[0 * NPTS + n] = w0;
        wout[1 * NPTS + n] = w1;
        wout[2 * NPTS + n] = w2;
        wout[3 * NPTS + n] = w3;
    }
}

// fused t = z + Lq and LayerNorm; one block per channel l; half2 reads
__global__ __launch_bounds__(256)
void layernorm_fused(const float* __restrict__ lnw, const float* __restrict__ lnb) {
    __shared__ float tbuf[NPTS];
    __shared__ float rs[8], rss[8];
    int l = blockIdx.x;
    const int NP2 = NPTS / 2;
    const size_t HS2 = (size_t)LCH * NP2;
    const __half2* k2  = (const __half2*)g_keys_h + (size_t)l * NP2;
    const __half2* lq2 = (const __half2*)g_Lq_h + (size_t)l * NP2;
    const float2* wm2  = (const float2*)g_wmap;
    float s = 0.f, ss = 0.f;
    for (int n2 = threadIdx.x; n2 < NP2; n2 += 256) {
        float2 w0 = wm2[0 * NP2 + n2];
        float2 w1 = wm2[1 * NP2 + n2];
        float2 w2 = wm2[2 * NP2 + n2];
        float2 w3 = wm2[3 * NP2 + n2];
        float2 k0 = __half22float2(k2[n2]);
        float2 k1 = __half22float2(k2[HS2 + n2]);
        float2 kk2 = __half22float2(k2[2 * HS2 + n2]);
        float2 k3 = __half22float2(k2[3 * HS2 + n2]);
        float2 lq = __half22float2(lq2[n2]);
        float tx = w0.x * k0.x + w1.x * k1.x + w2.x * kk2.x + w3.x * k3.x + lq.x;
        float ty = w0.y * k0.y + w1.y * k1.y + w2.y * kk2.y + w3.y * k3.y + lq.y;
        tbuf[2 * n2]     = tx;
        tbuf[2 * n2 + 1] = ty;
        s += tx + ty;
        ss += tx * tx + ty * ty;
    }
    for (int o = 16; o > 0; o >>= 1) {
        s  += __shfl_down_sync(0xffffffffu, s,  o);
        ss += __shfl_down_sync(0xffffffffu, ss, o);
    }
    int wid = threadIdx.x >> 5, lid = threadIdx.x & 31;
    if (lid == 0) { rs[wid] = s; rss[wid] = ss; }
    __syncthreads();
    if (wid == 0) {
        s  = (lid < 8) ? rs[lid]  : 0.f;
        ss = (lid < 8) ? rss[lid] : 0.f;
        for (int o = 4; o > 0; o >>= 1) {
            s  += __shfl_down_sync(0xffffffffu, s,  o);
            ss += __shfl_down_sync(0xffffffffu, ss, o);
        }
        if (lid == 0) { rs[0] = s; rss[0] = ss; }
    }
    __syncthreads();
    float mu = rs[0] * (1.0f / NPTS);
    float var = rss[0] * (1.0f / NPTS) - mu * mu;
    float rstd = rsqrtf(var + 1e-5f);
    float* row = g_t + (size_t)l * NPTS;
    for (int n = threadIdx.x; n < NPTS; n += 256)
        row[n] = (tbuf[n] - mu) * rstd * lnw[n] + lnb[n];
}

// ========================= launch ==========================================
extern "C" void kernel_launch(void* const* d_in, const int* in_sizes, int n_in,
                              void* d_out, int out_size) {
    const float* point_features = (const float*)d_in[0];
    const float* keypoints      = (const float*)d_in[1];
    const float* bev_features   = (const float*)d_in[2];
    const float* conv_L_w       = (const float*)d_in[3];
    const float* conv_L_b       = (const float*)d_in[4];
    const float* img_head_w     = (const float*)d_in[5];
    const float* img_head_b     = (const float*)d_in[6];
    const float* ln_w           = (const float*)d_in[7];
    const float* ln_b           = (const float*)d_in[8];
    const float* conv_fusion_w  = (const float*)d_in[9];
    const float* conv_fusion_b  = (const float*)d_in[10];
    float* out = (float*)d_out;

    cudaFuncSetAttribute(gemm_dual16,   cudaFuncAttributeMaxDynamicSharedMemorySize, D_SMEM);
    cudaFuncSetAttribute(gemm_single16, cudaFuncAttributeMaxDynamicSharedMemorySize, H_SMEM);

    float* p_t;
    cudaGetSymbolAddress((void**)&p_t, g_t);
    __half *wFh, *tTh, *pfTh;
    cudaGetSymbolAddress((void**)&wFh,  g_wF_h);
    cudaGetSymbolAddress((void**)&tTh,  g_tT_h);
    cudaGetSymbolAddress((void**)&pfTh, g_pfT_h);

    float* wout = (out_size >= LCH * NPTS + HEADS * NPTS)
                ? out + (size_t)LCH * NPTS : nullptr;

    // 1) BEV gather -> fp16 transposed directly
    gather_bevT<<<dim3(NPTS / 32, ICH / 32), 256>>>(bev_features, keypoints);
    // 2) weight converts (all fp16)
    {
        int count = HEADS * LCH * ICH + 2 * LCH * LCH;
        cvt_weights<<<(count + 255) / 256, 256>>>(img_head_w, conv_L_w, conv_fusion_w);
    }
    // 3) pf transpose -> fp16
    cvt_T16<<<dim3(NPTS / 32, LCH / 32), 256>>>(point_features, pfTh, LCH);
    // 4) keys + L_query fp16 GEMMs, 256x128 tiles  (profiled slot #4)
    gemm_dual16<<<320, 512, D_SMEM>>>(conv_L_b, img_head_b);
    // 5) partial scores
    score_part<<<dim3(NPTS / 512, 16), 256>>>();
    // 6) softmax over heads (+ weightmap output tail)
    softmax_k<<<NPTS / 256, 256>>>(wout);
    // 7) fused t + LayerNorm
    layernorm_fused<<<LCH, 256>>>(ln_w, ln_b);
    // 8) t transpose -> fp16
    cvt_T16<<<dim3(NPTS / 32, LCH / 32), 256>>>(p_t, tTh, LCH);
    // 9) fusion GEMM (fp16 in, fp32 out) -> out
    gemm_single16<<<dim3(NPTS / 128, LCH / 128), 256, H_SMEM>>>(
        wFh, tTh, conv_fusion_b, out, NPTS, LCH);
}